// round 9
// baseline (speedup 1.0000x reference)
#include <cuda_runtime.h>
#include <math.h>
#include <stdint.h>

#define Bsz 4
#define SRCL 256
#define TGTL 512
#define DMODEL 1024
#define NHEAD 16
#define DKH 64
#define NLAYER 8
#define DFF 4096
#define VOC 32000
#define NQ (Bsz*TGTL)
#define NE (Bsz*SRCL)

// ---------------- scratch (device globals; no allocations allowed) ----------
__device__ float g_x[NQ*DMODEL];
__device__ float g_enc[NE*DMODEL];
__device__ float g_q[NQ*DMODEL];
__device__ float g_k[NQ*DMODEL];
__device__ float g_v[NQ*DMODEL];
__device__ float g_attn[NQ*DMODEL];
__device__ float g_p0[NQ*DMODEL];
__device__ float g_p1[NQ*DMODEL];
__device__ float g_p2[NQ*DMODEL];
__device__ float g_p3[NQ*DMODEL];
__device__ float g_ffn[NQ*DFF];
__device__ float g_zero[DMODEL];   // zero-initialized: bias for split-K z>0

// ---------------- helpers ---------------------------------------------------
__device__ __forceinline__ float blkReduceSum(float v) {
    #pragma unroll
    for (int o = 16; o > 0; o >>= 1) v += __shfl_xor_sync(0xffffffffu, v, o);
    __shared__ float sm[8];
    int w = threadIdx.x >> 5, ln = threadIdx.x & 31;
    __syncthreads();
    if (ln == 0) sm[w] = v;
    __syncthreads();
    float r = sm[0];
    #pragma unroll
    for (int i = 1; i < 8; i++) r += sm[i];
    return r;
}

__device__ __forceinline__ uint32_t f2tf32(float f) {
    uint32_t u;
    asm("cvt.rna.tf32.f32 %0, %1;" : "=r"(u) : "f"(f));
    return u;
}

#define MMA_TF32(ACC, A0, A1, A2, A3, B0, B1)                                  \
    asm volatile(                                                              \
        "mma.sync.aligned.m16n8k8.row.col.f32.tf32.tf32.f32 "                  \
        "{%0,%1,%2,%3},{%4,%5,%6,%7},{%8,%9},{%0,%1,%2,%3};"                   \
        : "+f"((ACC)[0]), "+f"((ACC)[1]), "+f"((ACC)[2]), "+f"((ACC)[3])       \
        : "r"(A0), "r"(A1), "r"(A2), "r"(A3), "r"(B0), "r"(B1))

#define CP_ASYNC16(dst, src)                                                   \
    asm volatile("cp.async.ca.shared.global [%0], [%1], 16;" ::                \
                 "r"(dst), "l"(src))
#define CP_COMMIT() asm volatile("cp.async.commit_group;")
#define CP_WAIT2()  asm volatile("cp.async.wait_group 2;")

__device__ __forceinline__ float pe_val(int pos, int d) {
    float div = expf((float)(d & ~1) * (-9.210340371976184f / 1024.0f));
    float ang = (float)pos * div;
    return (d & 1) ? cosf(ang) : sinf(ang);
}

// ---------------- embedding / encoder PE ------------------------------------
__global__ void embed_kernel(const int* __restrict__ tgt,
                             const float* __restrict__ emb,
                             float* __restrict__ x) {
    int row = blockIdx.x;
    int t = row % TGTL;
    int tok = tgt[row];
    const float* er = emb + (size_t)tok * DMODEL;
    float* xr = x + (size_t)row * DMODEL;
    for (int d = threadIdx.x; d < DMODEL; d += blockDim.x)
        xr[d] = er[d] + pe_val(t, d);
}

__global__ void encpe_kernel(const float* __restrict__ src,
                             float* __restrict__ enc) {
    int row = blockIdx.x;
    int s = row % SRCL;
    const float* sr = src + (size_t)row * DMODEL;
    float* er = enc + (size_t)row * DMODEL;
    for (int d = threadIdx.x; d < DMODEL; d += blockDim.x)
        er[d] = sr[d] + pe_val(s, d);
}

// ---------------- TF32 GEMM: cp.async pipeline, z-batched / split-K ----------
// Per-z: C[z][M,N] += A[z][M,K]@W[z][K,N] + Bi[z]. lda = row stride of A
// (can differ from K for split-K slices). relu only valid when unsplit.
#define BMt 128
#define BNt 128
#define BKt 16
#define NSTG 4
#define AS_STRIDE 2560
#define BS_BASE   10240
#define BS_STRIDE 2176
#define GEMM_SMEM ((BS_BASE + NSTG*BS_STRIDE) * 4)

struct GArg4 {
    const float* A[4];
    const float* W[4];
    const float* Bi[4];
    float* C[4];
    int M[4];
};

__global__ void __launch_bounds__(256, 2)
gemm_tf32(GArg4 a4, int N, int K, int lda, int relu) {
    int z = blockIdx.z;
    const float* __restrict__ A = a4.A[z];
    const float* __restrict__ W = a4.W[z];
    const float* __restrict__ bias = a4.Bi[z];
    float* __restrict__ C = a4.C[z];
    int M = a4.M[z];

    int m0 = blockIdx.y * BMt, n0 = blockIdx.x * BNt;
    if (m0 >= M) return;

    extern __shared__ float smf[];
    uint32_t smem_u32 = (uint32_t)__cvta_generic_to_shared(smf);

    int tid = threadIdx.x;
    int warp = tid >> 5, lane = tid & 31;
    int g = lane >> 2, c = lane & 3;
    int wm = (warp & 1) * 64, wn = (warp >> 1) * 32;

    int arow = tid >> 1, acl = (tid & 1) * 2;
    const float* Asrc = A + (size_t)(m0 + arow) * lda + acl * 4;
    uint32_t Adst = smem_u32 + (arow * 20 + acl * 4) * 4;
    int brow = tid >> 4, bcl = (tid & 15) * 2;
    const float* Bsrc = W + (size_t)brow * N + n0 + bcl * 4;
    uint32_t Bdst = smem_u32 + (BS_BASE + brow * 136 + bcl * 4) * 4;

#define ISSUE_STAGE(S, K0)                                                     \
    do {                                                                       \
        uint32_t ad = Adst + (S) * (AS_STRIDE * 4);                            \
        const float* as = Asrc + (K0);                                         \
        CP_ASYNC16(ad, as);                                                    \
        CP_ASYNC16(ad + 16, as + 4);                                           \
        uint32_t bd = Bdst + (S) * (BS_STRIDE * 4);                            \
        const float* bs = Bsrc + (size_t)(K0) * N;                             \
        CP_ASYNC16(bd, bs);                                                    \
        CP_ASYNC16(bd + 16, bs + 4);                                           \
    } while (0)

    float acc[4][4][4] = {};

    int T = K / BKt;
    ISSUE_STAGE(0, 0); CP_COMMIT();
    ISSUE_STAGE(1, BKt); CP_COMMIT();
    ISSUE_STAGE(2, 2 * BKt); CP_COMMIT();

    for (int t = 0; t < T; t++) {
        CP_WAIT2();
        __syncthreads();
        if (t + 3 < T) ISSUE_STAGE((t + 3) & 3, (t + 3) * BKt);
        CP_COMMIT();

        const float* As = smf + (t & 3) * AS_STRIDE;
        const float* Bs = smf + BS_BASE + (t & 3) * BS_STRIDE;
        #pragma unroll
        for (int ks = 0; ks < 2; ks++) {
            int kb = ks * 8;
            uint32_t af[4][4], bf[4][2];
            #pragma unroll
            for (int im = 0; im < 4; im++) {
                int m = wm + im * 16 + g;
                af[im][0] = f2tf32(As[m * 20 + kb + c]);
                af[im][1] = f2tf32(As[(m + 8) * 20 + kb + c]);
                af[im][2] = f2tf32(As[m * 20 + kb + c + 4]);
                af[im][3] = f2tf32(As[(m + 8) * 20 + kb + c + 4]);
            }
            #pragma unroll
            for (int jn = 0; jn < 4; jn++) {
                int n = wn + jn * 8 + g;
                bf[jn][0] = f2tf32(Bs[(kb + c) * 136 + n]);
                bf[jn][1] = f2tf32(Bs[(kb + c + 4) * 136 + n]);
            }
            #pragma unroll
            for (int im = 0; im < 4; im++)
                #pragma unroll
                for (int jn = 0; jn < 4; jn++)
                    MMA_TF32(acc[im][jn], af[im][0], af[im][1], af[im][2],
                             af[im][3], bf[jn][0], bf[jn][1]);
        }
    }
#undef ISSUE_STAGE

    #pragma unroll
    for (int jn = 0; jn < 4; jn++) {
        int col = n0 + wn + jn * 8 + 2 * c;
        float b0v = __ldg(bias + col), b1v = __ldg(bias + col + 1);
        #pragma unroll
        for (int im = 0; im < 4; im++) {
            int row0 = m0 + wm + im * 16 + g;
            float v0 = acc[im][jn][0] + b0v;
            float v1 = acc[im][jn][1] + b1v;
            float v2 = acc[im][jn][2] + b0v;
            float v3 = acc[im][jn][3] + b1v;
            if (relu) {
                v0 = fmaxf(v0, 0.f); v1 = fmaxf(v1, 0.f);
                v2 = fmaxf(v2, 0.f); v3 = fmaxf(v3, 0.f);
            }
            *(float2*)(C + (size_t)row0 * N + col)       = make_float2(v0, v1);
            *(float2*)(C + (size_t)(row0 + 8) * N + col) = make_float2(v2, v3);
        }
    }
}

// ---------------- fused flash attention --------------------------------------
#define FLASH_SMEM ((64*68*2 + 64*72) * 4)

__global__ void __launch_bounds__(128)
flash_attn(const float* __restrict__ Q, const float* __restrict__ Kg,
           const float* __restrict__ Vg, float* __restrict__ O,
           int Sk, int causal, const int* __restrict__ tgt) {
    extern __shared__ uint32_t sm_u[];
    uint32_t (*Qs)[68]  = (uint32_t(*)[68])sm_u;
    uint32_t (*KPs)[68] = (uint32_t(*)[68])(sm_u + 64 * 68);
    uint32_t (*Vs)[72]  = (uint32_t(*)[72])(sm_u + 2 * 64 * 68);

    int qt = blockIdx.x, h = blockIdx.y, b = blockIdx.z;
    int tid = threadIdx.x, warp = tid >> 5, lane = tid & 31;
    int g = lane >> 2, c = lane & 3;
    int row = tid >> 1, kg = (tid & 1) * 32;
    int mw = warp * 16;

    const float* qp = Q + (size_t)(b * TGTL + qt * 64 + row) * DMODEL + h * 64 + kg;
    #pragma unroll
    for (int u = 0; u < 8; u++) {
        float4 qv = *(const float4*)(qp + u * 4);
        int cc = kg + u * 4;
        Qs[row][cc + 0] = f2tf32(qv.x); Qs[row][cc + 1] = f2tf32(qv.y);
        Qs[row][cc + 2] = f2tf32(qv.z); Qs[row][cc + 3] = f2tf32(qv.w);
    }

    int gi0 = qt * 64 + mw + g, gi1 = gi0 + 8;
    int ok0 = 1, ok1 = 1;
    if (causal) {
        ok0 = (tgt[b * TGTL + gi0] != 0);
        ok1 = (tgt[b * TGTL + gi1] != 0);
    }

    float m0r = -1e30f, m1r = -1e30f, l0 = 0.f, l1 = 0.f;
    float o[8][4] = {};

    int nkt = Sk >> 6;
    for (int kt = 0; kt < nkt; kt++) {
        bool skipk = (causal != 0) && (kt > qt);
        __syncthreads();
        const float* vp = Vg + (size_t)(b * Sk + kt * 64 + row) * DMODEL + h * 64 + kg;
        if (!skipk) {
            const float* kp = Kg + (size_t)(b * Sk + kt * 64 + row) * DMODEL + h * 64 + kg;
            #pragma unroll
            for (int u = 0; u < 8; u++) {
                float4 kv = *(const float4*)(kp + u * 4);
                int cc = kg + u * 4;
                KPs[row][cc + 0] = f2tf32(kv.x); KPs[row][cc + 1] = f2tf32(kv.y);
                KPs[row][cc + 2] = f2tf32(kv.z); KPs[row][cc + 3] = f2tf32(kv.w);
            }
        }
        #pragma unroll
        for (int u = 0; u < 8; u++) {
            float4 vv = *(const float4*)(vp + u * 4);
            int cc = kg + u * 4;
            Vs[row][cc + 0] = f2tf32(vv.x); Vs[row][cc + 1] = f2tf32(vv.y);
            Vs[row][cc + 2] = f2tf32(vv.z); Vs[row][cc + 3] = f2tf32(vv.w);
        }
        __syncthreads();

        float s[8][4];
        if (!skipk) {
            #pragma unroll
            for (int nb = 0; nb < 8; nb++)
                s[nb][0] = s[nb][1] = s[nb][2] = s[nb][3] = 0.f;
            #pragma unroll
            for (int kb = 0; kb < 64; kb += 8) {
                uint32_t a0 = Qs[mw + g][kb + c];
                uint32_t a1 = Qs[mw + g + 8][kb + c];
                uint32_t a2 = Qs[mw + g][kb + c + 4];
                uint32_t a3 = Qs[mw + g + 8][kb + c + 4];
                #pragma unroll
                for (int nb = 0; nb < 8; nb++) {
                    uint32_t b0 = KPs[nb * 8 + g][kb + c];
                    uint32_t b1 = KPs[nb * 8 + g][kb + c + 4];
                    MMA_TF32(s[nb], a0, a1, a2, a3, b0, b1);
                }
            }
            #pragma unroll
            for (int nb = 0; nb < 8; nb++) {
                int gj = kt * 64 + nb * 8 + 2 * c;
                s[nb][0] *= 0.125f; s[nb][1] *= 0.125f;
                s[nb][2] *= 0.125f; s[nb][3] *= 0.125f;
                if (causal) {
                    if (gj > gi0 || !ok0)     s[nb][0] = -1e9f;
                    if (gj + 1 > gi0 || !ok0) s[nb][1] = -1e9f;
                    if (gj > gi1 || !ok1)     s[nb][2] = -1e9f;
                    if (gj + 1 > gi1 || !ok1) s[nb][3] = -1e9f;
                }
            }
        } else {
            #pragma unroll
            for (int nb = 0; nb < 8; nb++)
                s[nb][0] = s[nb][1] = s[nb][2] = s[nb][3] = -1e9f;
        }

        float t0 = -1e30f, t1 = -1e30f;
        #pragma unroll
        for (int nb = 0; nb < 8; nb++) {
            t0 = fmaxf(t0, fmaxf(s[nb][0], s[nb][1]));
            t1 = fmaxf(t1, fmaxf(s[nb][2], s[nb][3]));
        }
        t0 = fmaxf(t0, __shfl_xor_sync(0xffffffffu, t0, 1));
        t0 = fmaxf(t0, __shfl_xor_sync(0xffffffffu, t0, 2));
        t1 = fmaxf(t1, __shfl_xor_sync(0xffffffffu, t1, 1));
        t1 = fmaxf(t1, __shfl_xor_sync(0xffffffffu, t1, 2));
        float nm0 = fmaxf(m0r, t0), nm1 = fmaxf(m1r, t1);
        float f0 = __expf(m0r - nm0), f1 = __expf(m1r - nm1);
        float ts0 = 0.f, ts1 = 0.f;
        #pragma unroll
        for (int nb = 0; nb < 8; nb++) {
            s[nb][0] = __expf(s[nb][0] - nm0);
            s[nb][1] = __expf(s[nb][1] - nm0);
            s[nb][2] = __expf(s[nb][2] - nm1);
            s[nb][3] = __expf(s[nb][3] - nm1);
            ts0 += s[nb][0] + s[nb][1];
            ts1 += s[nb][2] + s[nb][3];
        }
        ts0 += __shfl_xor_sync(0xffffffffu, ts0, 1);
        ts0 += __shfl_xor_sync(0xffffffffu, ts0, 2);
        ts1 += __shfl_xor_sync(0xffffffffu, ts1, 1);
        ts1 += __shfl_xor_sync(0xffffffffu, ts1, 2);
        l0 = l0 * f0 + ts0;
        l1 = l1 * f1 + ts1;
        m0r = nm0; m1r = nm1;
        #pragma unroll
        for (int nb = 0; nb < 8; nb++) {
            o[nb][0] *= f0; o[nb][1] *= f0;
            o[nb][2] *= f1; o[nb][3] *= f1;
        }
        __syncthreads();
        #pragma unroll
        for (int nb = 0; nb < 8; nb++) {
            int cc = nb * 8 + 2 * c;
            KPs[mw + g][cc]     = f2tf32(s[nb][0]);
            KPs[mw + g][cc + 1] = f2tf32(s[nb][1]);
            KPs[mw + g + 8][cc]     = f2tf32(s[nb][2]);
            KPs[mw + g + 8][cc + 1] = f2tf32(s[nb][3]);
        }
        __syncthreads();
        #pragma unroll
        for (int kb = 0; kb < 64; kb += 8) {
            uint32_t a0 = KPs[mw + g][kb + c];
            uint32_t a1 = KPs[mw + g + 8][kb + c];
            uint32_t a2 = KPs[mw + g][kb + c + 4];
            uint32_t a3 = KPs[mw + g + 8][kb + c + 4];
            #pragma unroll
            for (int nb = 0; nb < 8; nb++) {
                uint32_t b0 = Vs[kb + c][nb * 8 + g];
                uint32_t b1 = Vs[kb + c + 4][nb * 8 + g];
                MMA_TF32(o[nb], a0, a1, a2, a3, b0, b1);
            }
        }
    }

    float inv0 = 1.0f / l0, inv1 = 1.0f / l1;
    #pragma unroll
    for (int nb = 0; nb < 8; nb++) {
        int col = h * 64 + nb * 8 + 2 * c;
        size_t r0 = (size_t)(b * TGTL + qt * 64 + mw + g);
        *(float2*)(O + r0 * DMODEL + col) =
            make_float2(o[nb][0] * inv0, o[nb][1] * inv0);
        *(float2*)(O + (r0 + 8) * DMODEL + col) =
            make_float2(o[nb][2] * inv1, o[nb][3] * inv1);
    }
}

// ---------------- fused 4-way split-K reduce + residual + LayerNorm ----------
// x = LN(x + p0 + p1 + p2 + p3)
__global__ void ln_res4(float* __restrict__ x,
                        const float* __restrict__ p0, const float* __restrict__ p1,
                        const float* __restrict__ p2, const float* __restrict__ p3,
                        const float* __restrict__ g, const float* __restrict__ bb) {
    int row = blockIdx.x, tid = threadIdx.x;
    size_t off = (size_t)row * DMODEL;
    float4* xr4 = (float4*)(x + off);
    float4 v = xr4[tid];
    float4 a0 = ((const float4*)(p0 + off))[tid];
    float4 a1 = ((const float4*)(p1 + off))[tid];
    float4 a2 = ((const float4*)(p2 + off))[tid];
    float4 a3 = ((const float4*)(p3 + off))[tid];
    v.x += a0.x + a1.x + a2.x + a3.x;
    v.y += a0.y + a1.y + a2.y + a3.y;
    v.z += a0.z + a1.z + a2.z + a3.z;
    v.w += a0.w + a1.w + a2.w + a3.w;
    float s = v.x + v.y + v.z + v.w;
    s = blkReduceSum(s);
    float mu = s * (1.0f / DMODEL);
    float dx = v.x - mu, dy = v.y - mu, dz = v.z - mu, dw = v.w - mu;
    float q = dx * dx + dy * dy + dz * dz + dw * dw;
    q = blkReduceSum(q);
    float rs = rsqrtf(q * (1.0f / DMODEL) + 1e-5f);
    float4 gv = ((const float4*)g)[tid];
    float4 bv = ((const float4*)bb)[tid];
    float4 o;
    o.x = dx * rs * gv.x + bv.x;
    o.y = dy * rs * gv.y + bv.y;
    o.z = dz * rs * gv.z + bv.z;
    o.w = dw * rs * gv.w + bv.w;
    xr4[tid] = o;
}

// ---------------- host orchestration ----------------------------------------
static inline GArg4 g1(const float* A, const float* W, const float* B, float* C,
                       int M) {
    GArg4 t;
    for (int i = 0; i < 4; i++) {
        t.A[i] = A; t.W[i] = W; t.Bi[i] = B; t.C[i] = C; t.M[i] = M;
    }
    return t;
}

extern "C" void kernel_launch(void* const* d_in, const int* in_sizes, int n_in,
                              void* d_out, int out_size) {
    (void)n_in; (void)out_size;
    int dict = (in_sizes[3] == 32768000);
    int base, iFCW, iFCB, iN1G, iN1B, iN2G, iN2B, iN3G, iN3B;
    if (dict) {
        iFCW = 3; iFCB = 4; base = 5;
        iN1G = base + 20; iN2G = base + 21; iN3G = base + 22;
        iN1B = base + 23; iN2B = base + 24; iN3B = base + 25;
    } else {
        base = 3; iFCW = 29; iFCB = 30;
        iN1G = base + 20; iN1B = base + 21; iN2G = base + 22;
        iN2B = base + 23; iN3G = base + 24; iN3B = base + 25;
    }
    const float* src  = (const float*)d_in[0];
    const int*   tgt  = (const int*)d_in[1];
    const float* emb  = (const float*)d_in[2];
    const float* fcw  = (const float*)d_in[iFCW];
    const float* fcb  = (const float*)d_in[iFCB];
    const float* AP[16];
    for (int i = 0; i < 16; i++) AP[i] = (const float*)d_in[base + i];
    const float* w1 = (const float*)d_in[base + 16];
    const float* b1 = (const float*)d_in[base + 17];
    const float* w2 = (const float*)d_in[base + 18];
    const float* b2 = (const float*)d_in[base + 19];
    const float* n1g = (const float*)d_in[iN1G];
    const float* n1b = (const float*)d_in[iN1B];
    const float* n2g = (const float*)d_in[iN2G];
    const float* n2b = (const float*)d_in[iN2B];
    const float* n3g = (const float*)d_in[iN3G];
    const float* n3b = (const float*)d_in[iN3B];

    float *x, *enc, *q, *k, *v, *attn, *ffn, *zero;
    float* P[4];
    cudaGetSymbolAddress((void**)&x,    g_x);
    cudaGetSymbolAddress((void**)&enc,  g_enc);
    cudaGetSymbolAddress((void**)&q,    g_q);
    cudaGetSymbolAddress((void**)&k,    g_k);
    cudaGetSymbolAddress((void**)&v,    g_v);
    cudaGetSymbolAddress((void**)&attn, g_attn);
    cudaGetSymbolAddress((void**)&P[0], g_p0);
    cudaGetSymbolAddress((void**)&P[1], g_p1);
    cudaGetSymbolAddress((void**)&P[2], g_p2);
    cudaGetSymbolAddress((void**)&P[3], g_p3);
    cudaGetSymbolAddress((void**)&ffn,  g_ffn);
    cudaGetSymbolAddress((void**)&zero, g_zero);

    cudaFuncSetAttribute(gemm_tf32, cudaFuncAttributeMaxDynamicSharedMemorySize,
                         GEMM_SMEM);
    cudaFuncSetAttribute(flash_attn, cudaFuncAttributeMaxDynamicSharedMemorySize,
                         FLASH_SMEM);

    encpe_kernel<<<NE, 256>>>(src, enc);
    embed_kernel<<<NQ, 256>>>(tgt, emb, x);

    dim3 gDD4(DMODEL / BNt, NQ / BMt, 4);  // split-K x4 grids
    dim3 gDD3(DMODEL / BNt, NQ / BMt, 3);  // batched QKV
    dim3 gFF(DFF / BNt, NQ / BMt, 1);

    // split-K builder: A strip z*KS cols, W strip z*KS rows, bias only in z=0
    auto gsplit = [&](const float* A, const float* W, const float* bias,
                      int M, int N, int KS) {
        GArg4 t;
        for (int zz = 0; zz < 4; zz++) {
            t.A[zz] = A + (size_t)zz * KS;
            t.W[zz] = W + (size_t)zz * KS * N;
            t.Bi[zz] = (zz == 0) ? bias : zero;
            t.C[zz] = P[zz];
            t.M[zz] = M;
        }
        return t;
    };

    for (int l = 0; l < NLAYER; l++) {
        size_t ow = (size_t)l * DMODEL * DMODEL, ob = (size_t)l * DMODEL;
        size_t ow1 = (size_t)l * DMODEL * DFF, ob1 = (size_t)l * DFF;

        // ---- self attention: batched QKV ----
        GArg4 qkv = g1(x, AP[0] + ow, AP[1] + ob, q, NQ);
        qkv.W[1] = AP[2] + ow; qkv.Bi[1] = AP[3] + ob; qkv.C[1] = k;
        qkv.W[2] = AP[4] + ow; qkv.Bi[2] = AP[5] + ob; qkv.C[2] = v;
        gemm_tf32<<<gDD3, 256, GEMM_SMEM>>>(qkv, DMODEL, DMODEL, DMODEL, 0);
        flash_attn<<<dim3(8, NHEAD, Bsz), 128, FLASH_SMEM>>>(q, k, v, attn,
                                                             TGTL, 1, tgt);
        // proj: split-K x4 (K=1024 -> 4x256)
        gemm_tf32<<<gDD4, 256, GEMM_SMEM>>>(
            gsplit(attn, AP[6] + ow, AP[7] + ob, NQ, DMODEL, 256),
            DMODEL, 256, DMODEL, 0);
        ln_res4<<<NQ, 256>>>(x, P[0], P[1], P[2], P[3], n1g + ob, n1b + ob);

        // ---- cross attention: fused Q (on x) + K,V (on enc) ----
        GArg4 ckv = g1(x, AP[8] + ow, AP[9] + ob, q, NQ);
        ckv.A[1] = enc; ckv.W[1] = AP[10] + ow; ckv.Bi[1] = AP[11] + ob; ckv.C[1] = k; ckv.M[1] = NE;
        ckv.A[2] = enc; ckv.W[2] = AP[12] + ow; ckv.Bi[2] = AP[13] + ob; ckv.C[2] = v; ckv.M[2] = NE;
        gemm_tf32<<<gDD3, 256, GEMM_SMEM>>>(ckv, DMODEL, DMODEL, DMODEL, 0);
        flash_attn<<<dim3(8, NHEAD, Bsz), 128, FLASH_SMEM>>>(q, k, v, attn,
                                                             SRCL, 0, tgt);
        gemm_tf32<<<gDD4, 256, GEMM_SMEM>>>(
            gsplit(attn, AP[14] + ow, AP[15] + ob, NQ, DMODEL, 256),
            DMODEL, 256, DMODEL, 0);
        ln_res4<<<NQ, 256>>>(x, P[0], P[1], P[2], P[3], n2g + ob, n2b + ob);

        // ---- feed forward ----
        gemm_tf32<<<gFF, 256, GEMM_SMEM>>>(
            g1(x, w1 + ow1, b1 + ob1, ffn, NQ), DFF, DMODEL, DMODEL, 1);
        // w2: split-K x4 (K=4096 -> 4x1024)
        gemm_tf32<<<gDD4, 256, GEMM_SMEM>>>(
            gsplit(ffn, w2 + ow1, b2 + ob, NQ, DMODEL, 1024),
            DMODEL, 1024, DFF, 0);
        ln_res4<<<NQ, 256>>>(x, P[0], P[1], P[2], P[3], n3g + ob, n3b + ob);
    }

    // ---- final projection to vocab ----
    gemm_tf32<<<dim3(VOC / BNt, NQ / BMt, 1), 256, GEMM_SMEM>>>(
        g1(x, fcw, fcb, (float*)d_out, NQ), VOC, DMODEL, DMODEL, 0);
}

// round 12
// speedup vs baseline: 1.4962x; 1.4962x over previous
#include <cuda_runtime.h>
#include <math.h>
#include <stdint.h>

#define Bsz 4
#define SRCL 256
#define TGTL 512
#define DMODEL 1024
#define NHEAD 16
#define DKH 64
#define NLAYER 8
#define DFF 4096
#define VOC 32000
#define NQ (Bsz*TGTL)
#define NE (Bsz*SRCL)

// weight-scratch offsets (floats)
#define WT_ATTN_TENSOR (NLAYER*DMODEL*DMODEL)            // 8388608 per tensor
#define WT_OFF_W1   (8u*WT_ATTN_TENSOR)                  // 67108864
#define WT_OFF_W2   (WT_OFF_W1 + NLAYER*DMODEL*DFF)      // 100663296
#define WT_OFF_FCW  (WT_OFF_W2 + NLAYER*DFF*DMODEL)      // 134217728
#define WT_TOTAL    (WT_OFF_FCW + DMODEL*VOC)            // 166985728

// ---------------- scratch (device globals; no allocations allowed) ----------
__device__ float g_x[NQ*DMODEL];
__device__ float g_xt[NQ*DMODEL];      // tf32-rounded copy of x (GEMM A input)
__device__ float g_enc[NE*DMODEL];
__device__ float g_enct[NE*DMODEL];    // tf32-rounded copy of enc
__device__ float g_q[NQ*DMODEL];
__device__ float g_k[NQ*DMODEL];
__device__ float g_v[NQ*DMODEL];
__device__ float g_attn[NQ*DMODEL];
__device__ float g_proj[NQ*DMODEL];
__device__ float g_ffn[NQ*DFF];
__device__ float g_wt[WT_TOTAL];       // tf32-rounded weights

// ---------------- helpers ---------------------------------------------------
__device__ __forceinline__ float blkReduceSum(float v) {
    #pragma unroll
    for (int o = 16; o > 0; o >>= 1) v += __shfl_xor_sync(0xffffffffu, v, o);
    __shared__ float sm[8];
    int w = threadIdx.x >> 5, ln = threadIdx.x & 31;
    __syncthreads();
    if (ln == 0) sm[w] = v;
    __syncthreads();
    float r = sm[0];
    #pragma unroll
    for (int i = 1; i < 8; i++) r += sm[i];
    return r;
}

__device__ __forceinline__ uint32_t f2tf32(float f) {
    uint32_t u;
    asm("cvt.rna.tf32.f32 %0, %1;" : "=r"(u) : "f"(f));
    return u;
}
__device__ __forceinline__ float tf32r(float f) {
    return __uint_as_float(f2tf32(f));
}

#define MMA_TF32(ACC, A0, A1, A2, A3, B0, B1)                                  \
    asm volatile(                                                              \
        "mma.sync.aligned.m16n8k8.row.col.f32.tf32.tf32.f32 "                  \
        "{%0,%1,%2,%3},{%4,%5,%6,%7},{%8,%9},{%0,%1,%2,%3};"                   \
        : "+f"((ACC)[0]), "+f"((ACC)[1]), "+f"((ACC)[2]), "+f"((ACC)[3])       \
        : "r"(A0), "r"(A1), "r"(A2), "r"(A3), "r"(B0), "r"(B1))

#define CP_ASYNC16(dst, src)                                                   \
    asm volatile("cp.async.ca.shared.global [%0], [%1], 16;" ::                \
                 "r"(dst), "l"(src))
#define CP_COMMIT() asm volatile("cp.async.commit_group;")
#define CP_WAIT2()  asm volatile("cp.async.wait_group 2;")

__device__ __forceinline__ float pe_val(int pos, int d) {
    float div = expf((float)(d & ~1) * (-9.210340371976184f / 1024.0f));
    float ang = (float)pos * div;
    return (d & 1) ? cosf(ang) : sinf(ang);
}

// ---------------- weight tf32 pre-round -------------------------------------
__global__ void cvt_tf32(const float* __restrict__ s, float* __restrict__ d,
                         int n4) {
    int i = blockIdx.x * blockDim.x + threadIdx.x;
    if (i >= n4) return;
    float4 v = ((const float4*)s)[i];
    v.x = tf32r(v.x); v.y = tf32r(v.y); v.z = tf32r(v.z); v.w = tf32r(v.w);
    ((float4*)d)[i] = v;
}

// ---------------- embedding / encoder PE ------------------------------------
__global__ void embed_kernel(const int* __restrict__ tgt,
                             const float* __restrict__ emb,
                             float* __restrict__ x, float* __restrict__ xt) {
    int row = blockIdx.x;
    int t = row % TGTL;
    int tok = tgt[row];
    const float* er = emb + (size_t)tok * DMODEL;
    float* xr = x + (size_t)row * DMODEL;
    float* xtr = xt + (size_t)row * DMODEL;
    for (int d = threadIdx.x; d < DMODEL; d += blockDim.x) {
        float v = er[d] + pe_val(t, d);
        xr[d] = v;
        xtr[d] = tf32r(v);
    }
}

__global__ void encpe_kernel(const float* __restrict__ src,
                             float* __restrict__ enc, float* __restrict__ enct) {
    int row = blockIdx.x;
    int s = row % SRCL;
    const float* sr = src + (size_t)row * DMODEL;
    float* er = enc + (size_t)row * DMODEL;
    float* etr = enct + (size_t)row * DMODEL;
    for (int d = threadIdx.x; d < DMODEL; d += blockDim.x) {
        float v = sr[d] + pe_val(s, d);
        er[d] = v;
        etr[d] = tf32r(v);
    }
}

// ---------------- TF32 GEMM: cp.async pipeline, z-batched, pre-rounded -------
// A and W must already be tf32-rounded fp32. cvtout rounds C for GEMM reuse.
#define BMt 128
#define BNt 128
#define BKt 16
#define NSTG 4
#define AS_STRIDE 2560
#define BS_BASE   10240
#define BS_STRIDE 2176
#define GEMM_SMEM ((BS_BASE + NSTG*BS_STRIDE) * 4)

struct GArg3 {
    const float* A[3];
    const float* W[3];
    const float* Bi[3];
    float* C[3];
    int M[3];
};

__global__ void __launch_bounds__(256, 2)
gemm_tf32(GArg3 a3, int N, int K, int relu, int cvtout) {
    int z = blockIdx.z;
    const float* __restrict__ A = a3.A[z];
    const float* __restrict__ W = a3.W[z];
    const float* __restrict__ bias = a3.Bi[z];
    float* __restrict__ C = a3.C[z];
    int M = a3.M[z];

    int m0 = blockIdx.y * BMt, n0 = blockIdx.x * BNt;
    if (m0 >= M) return;

    extern __shared__ float smf[];
    uint32_t smem_u32 = (uint32_t)__cvta_generic_to_shared(smf);

    int tid = threadIdx.x;
    int warp = tid >> 5, lane = tid & 31;
    int g = lane >> 2, c = lane & 3;
    int wm = (warp & 1) * 64, wn = (warp >> 1) * 32;

    int arow = tid >> 1, acl = (tid & 1) * 2;
    const float* Asrc = A + (size_t)(m0 + arow) * K + acl * 4;
    uint32_t Adst = smem_u32 + (arow * 20 + acl * 4) * 4;
    int brow = tid >> 4, bcl = (tid & 15) * 2;
    const float* Bsrc = W + (size_t)brow * N + n0 + bcl * 4;
    uint32_t Bdst = smem_u32 + (BS_BASE + brow * 136 + bcl * 4) * 4;

#define ISSUE_STAGE(S, K0)                                                     \
    do {                                                                       \
        uint32_t ad = Adst + (S) * (AS_STRIDE * 4);                            \
        const float* as = Asrc + (K0);                                         \
        CP_ASYNC16(ad, as);                                                    \
        CP_ASYNC16(ad + 16, as + 4);                                           \
        uint32_t bd = Bdst + (S) * (BS_STRIDE * 4);                            \
        const float* bs = Bsrc + (size_t)(K0) * N;                             \
        CP_ASYNC16(bd, bs);                                                    \
        CP_ASYNC16(bd + 16, bs + 4);                                           \
    } while (0)

    float acc[4][4][4] = {};

    int T = K / BKt;
    ISSUE_STAGE(0, 0); CP_COMMIT();
    ISSUE_STAGE(1, BKt); CP_COMMIT();
    ISSUE_STAGE(2, 2 * BKt); CP_COMMIT();

    const uint32_t* smu = (const uint32_t*)smf;
    for (int t = 0; t < T; t++) {
        CP_WAIT2();
        __syncthreads();
        if (t + 3 < T) ISSUE_STAGE((t + 3) & 3, (t + 3) * BKt);
        CP_COMMIT();

        const uint32_t* As = smu + (t & 3) * AS_STRIDE;
        const uint32_t* Bs = smu + BS_BASE + (t & 3) * BS_STRIDE;
        #pragma unroll
        for (int ks = 0; ks < 2; ks++) {
            int kb = ks * 8;
            uint32_t af[4][4], bf[4][2];
            #pragma unroll
            for (int im = 0; im < 4; im++) {
                int m = wm + im * 16 + g;
                af[im][0] = As[m * 20 + kb + c];
                af[im][1] = As[(m + 8) * 20 + kb + c];
                af[im][2] = As[m * 20 + kb + c + 4];
                af[im][3] = As[(m + 8) * 20 + kb + c + 4];
            }
            #pragma unroll
            for (int jn = 0; jn < 4; jn++) {
                int n = wn + jn * 8 + g;
                bf[jn][0] = Bs[(kb + c) * 136 + n];
                bf[jn][1] = Bs[(kb + c + 4) * 136 + n];
            }
            #pragma unroll
            for (int im = 0; im < 4; im++)
                #pragma unroll
                for (int jn = 0; jn < 4; jn++)
                    MMA_TF32(acc[im][jn], af[im][0], af[im][1], af[im][2],
                             af[im][3], bf[jn][0], bf[jn][1]);
        }
    }
#undef ISSUE_STAGE

    #pragma unroll
    for (int jn = 0; jn < 4; jn++) {
        int col = n0 + wn + jn * 8 + 2 * c;
        float b0v = __ldg(bias + col), b1v = __ldg(bias + col + 1);
        #pragma unroll
        for (int im = 0; im < 4; im++) {
            int row0 = m0 + wm + im * 16 + g;
            float v0 = acc[im][jn][0] + b0v;
            float v1 = acc[im][jn][1] + b1v;
            float v2 = acc[im][jn][2] + b0v;
            float v3 = acc[im][jn][3] + b1v;
            if (relu) {
                v0 = fmaxf(v0, 0.f); v1 = fmaxf(v1, 0.f);
                v2 = fmaxf(v2, 0.f); v3 = fmaxf(v3, 0.f);
            }
            if (cvtout) {
                v0 = tf32r(v0); v1 = tf32r(v1);
                v2 = tf32r(v2); v3 = tf32r(v3);
            }
            *(float2*)(C + (size_t)row0 * N + col)       = make_float2(v0, v1);
            *(float2*)(C + (size_t)(row0 + 8) * N + col) = make_float2(v2, v3);
        }
    }
}

// ---------------- fused flash attention --------------------------------------
// Q/K/V arrive tf32-pre-rounded (qkv GEMM cvtout=1) -> staging is bit-copy.
// Output attn is rounded here (feeds the proj GEMM as A).
#define FLASH_SMEM ((64*68*2 + 64*72) * 4)

__global__ void __launch_bounds__(128)
flash_attn(const float* __restrict__ Q, const float* __restrict__ Kg,
           const float* __restrict__ Vg, float* __restrict__ O,
           int Sk, int causal, const int* __restrict__ tgt) {
    extern __shared__ uint32_t sm_u[];
    uint32_t (*Qs)[68]  = (uint32_t(*)[68])sm_u;
    uint32_t (*KPs)[68] = (uint32_t(*)[68])(sm_u + 64 * 68);
    uint32_t (*Vs)[72]  = (uint32_t(*)[72])(sm_u + 2 * 64 * 68);

    int qt = blockIdx.x, h = blockIdx.y, b = blockIdx.z;
    int tid = threadIdx.x, warp = tid >> 5, lane = tid & 31;
    int g = lane >> 2, c = lane & 3;
    int row = tid >> 1, kg = (tid & 1) * 32;
    int mw = warp * 16;

    const float* qp = Q + (size_t)(b * TGTL + qt * 64 + row) * DMODEL + h * 64 + kg;
    #pragma unroll
    for (int u = 0; u < 8; u++) {
        float4 qv = *(const float4*)(qp + u * 4);
        int cc = kg + u * 4;
        Qs[row][cc + 0] = __float_as_uint(qv.x);
        Qs[row][cc + 1] = __float_as_uint(qv.y);
        Qs[row][cc + 2] = __float_as_uint(qv.z);
        Qs[row][cc + 3] = __float_as_uint(qv.w);
    }

    int gi0 = qt * 64 + mw + g, gi1 = gi0 + 8;
    int ok0 = 1, ok1 = 1;
    if (causal) {
        ok0 = (tgt[b * TGTL + gi0] != 0);
        ok1 = (tgt[b * TGTL + gi1] != 0);
    }

    float m0r = -1e30f, m1r = -1e30f, l0 = 0.f, l1 = 0.f;
    float o[8][4] = {};

    int nkt = Sk >> 6;
    for (int kt = 0; kt < nkt; kt++) {
        bool skipk = (causal != 0) && (kt > qt);
        __syncthreads();
        const float* vp = Vg + (size_t)(b * Sk + kt * 64 + row) * DMODEL + h * 64 + kg;
        if (!skipk) {
            const float* kp = Kg + (size_t)(b * Sk + kt * 64 + row) * DMODEL + h * 64 + kg;
            #pragma unroll
            for (int u = 0; u < 8; u++) {
                float4 kv = *(const float4*)(kp + u * 4);
                int cc = kg + u * 4;
                KPs[row][cc + 0] = __float_as_uint(kv.x);
                KPs[row][cc + 1] = __float_as_uint(kv.y);
                KPs[row][cc + 2] = __float_as_uint(kv.z);
                KPs[row][cc + 3] = __float_as_uint(kv.w);
            }
        }
        #pragma unroll
        for (int u = 0; u < 8; u++) {
            float4 vv = *(const float4*)(vp + u * 4);
            int cc = kg + u * 4;
            Vs[row][cc + 0] = __float_as_uint(vv.x);
            Vs[row][cc + 1] = __float_as_uint(vv.y);
            Vs[row][cc + 2] = __float_as_uint(vv.z);
            Vs[row][cc + 3] = __float_as_uint(vv.w);
        }
        __syncthreads();

        float s[8][4];
        if (!skipk) {
            #pragma unroll
            for (int nb = 0; nb < 8; nb++)
                s[nb][0] = s[nb][1] = s[nb][2] = s[nb][3] = 0.f;
            #pragma unroll
            for (int kb = 0; kb < 64; kb += 8) {
                uint32_t a0 = Qs[mw + g][kb + c];
                uint32_t a1 = Qs[mw + g + 8][kb + c];
                uint32_t a2 = Qs[mw + g][kb + c + 4];
                uint32_t a3 = Qs[mw + g + 8][kb + c + 4];
                #pragma unroll
                for (int nb = 0; nb < 8; nb++) {
                    uint32_t b0 = KPs[nb * 8 + g][kb + c];
                    uint32_t b1 = KPs[nb * 8 + g][kb + c + 4];
                    MMA_TF32(s[nb], a0, a1, a2, a3, b0, b1);
                }
            }
            #pragma unroll
            for (int nb = 0; nb < 8; nb++) {
                int gj = kt * 64 + nb * 8 + 2 * c;
                s[nb][0] *= 0.125f; s[nb][1] *= 0.125f;
                s[nb][2] *= 0.125f; s[nb][3] *= 0.125f;
                if (causal) {
                    if (gj > gi0 || !ok0)     s[nb][0] = -1e9f;
                    if (gj + 1 > gi0 || !ok0) s[nb][1] = -1e9f;
                    if (gj > gi1 || !ok1)     s[nb][2] = -1e9f;
                    if (gj + 1 > gi1 || !ok1) s[nb][3] = -1e9f;
                }
            }
        } else {
            #pragma unroll
            for (int nb = 0; nb < 8; nb++)
                s[nb][0] = s[nb][1] = s[nb][2] = s[nb][3] = -1e9f;
        }

        float t0 = -1e30f, t1 = -1e30f;
        #pragma unroll
        for (int nb = 0; nb < 8; nb++) {
            t0 = fmaxf(t0, fmaxf(s[nb][0], s[nb][1]));
            t1 = fmaxf(t1, fmaxf(s[nb][2], s[nb][3]));
        }
        t0 = fmaxf(t0, __shfl_xor_sync(0xffffffffu, t0, 1));
        t0 = fmaxf(t0, __shfl_xor_sync(0xffffffffu, t0, 2));
        t1 = fmaxf(t1, __shfl_xor_sync(0xffffffffu, t1, 1));
        t1 = fmaxf(t1, __shfl_xor_sync(0xffffffffu, t1, 2));
        float nm0 = fmaxf(m0r, t0), nm1 = fmaxf(m1r, t1);
        float f0 = __expf(m0r - nm0), f1 = __expf(m1r - nm1);
        float ts0 = 0.f, ts1 = 0.f;
        #pragma unroll
        for (int nb = 0; nb < 8; nb++) {
            s[nb][0] = __expf(s[nb][0] - nm0);
            s[nb][1] = __expf(s[nb][1] - nm0);
            s[nb][2] = __expf(s[nb][2] - nm1);
            s[nb][3] = __expf(s[nb][3] - nm1);
            ts0 += s[nb][0] + s[nb][1];
            ts1 += s[nb][2] + s[nb][3];
        }
        ts0 += __shfl_xor_sync(0xffffffffu, ts0, 1);
        ts0 += __shfl_xor_sync(0xffffffffu, ts0, 2);
        ts1 += __shfl_xor_sync(0xffffffffu, ts1, 1);
        ts1 += __shfl_xor_sync(0xffffffffu, ts1, 2);
        l0 = l0 * f0 + ts0;
        l1 = l1 * f1 + ts1;
        m0r = nm0; m1r = nm1;
        #pragma unroll
        for (int nb = 0; nb < 8; nb++) {
            o[nb][0] *= f0; o[nb][1] *= f0;
            o[nb][2] *= f1; o[nb][3] *= f1;
        }
        __syncthreads();
        #pragma unroll
        for (int nb = 0; nb < 8; nb++) {
            int cc = nb * 8 + 2 * c;
            KPs[mw + g][cc]     = f2tf32(s[nb][0]);
            KPs[mw + g][cc + 1] = f2tf32(s[nb][1]);
            KPs[mw + g + 8][cc]     = f2tf32(s[nb][2]);
            KPs[mw + g + 8][cc + 1] = f2tf32(s[nb][3]);
        }
        __syncthreads();
        #pragma unroll
        for (int kb = 0; kb < 64; kb += 8) {
            uint32_t a0 = KPs[mw + g][kb + c];
            uint32_t a1 = KPs[mw + g + 8][kb + c];
            uint32_t a2 = KPs[mw + g][kb + c + 4];
            uint32_t a3 = KPs[mw + g + 8][kb + c + 4];
            #pragma unroll
            for (int nb = 0; nb < 8; nb++) {
                uint32_t b0 = Vs[kb + c][nb * 8 + g];
                uint32_t b1 = Vs[kb + c + 4][nb * 8 + g];
                MMA_TF32(o[nb], a0, a1, a2, a3, b0, b1);
            }
        }
    }

    float inv0 = 1.0f / l0, inv1 = 1.0f / l1;
    #pragma unroll
    for (int nb = 0; nb < 8; nb++) {
        int col = h * 64 + nb * 8 + 2 * c;
        size_t r0 = (size_t)(b * TGTL + qt * 64 + mw + g);
        *(float2*)(O + r0 * DMODEL + col) =
            make_float2(tf32r(o[nb][0] * inv0), tf32r(o[nb][1] * inv0));
        *(float2*)(O + (r0 + 8) * DMODEL + col) =
            make_float2(tf32r(o[nb][2] * inv1), tf32r(o[nb][3] * inv1));
    }
}

// ---------------- fused residual + LayerNorm; writes x and tf32 copy ---------
__global__ void ln_res(float* __restrict__ x, const float* __restrict__ a,
                       const float* __restrict__ g, const float* __restrict__ bb,
                       float* __restrict__ xt) {
    int row = blockIdx.x, tid = threadIdx.x;
    size_t off = (size_t)row * DMODEL;
    float4* xr4 = (float4*)(x + off);
    const float4* ar4 = (const float4*)(a + off);
    float4 v = xr4[tid];
    float4 av = ar4[tid];
    v.x += av.x; v.y += av.y; v.z += av.z; v.w += av.w;
    float s = v.x + v.y + v.z + v.w;
    s = blkReduceSum(s);
    float mu = s * (1.0f / DMODEL);
    float dx = v.x - mu, dy = v.y - mu, dz = v.z - mu, dw = v.w - mu;
    float q = dx * dx + dy * dy + dz * dz + dw * dw;
    q = blkReduceSum(q);
    float rs = rsqrtf(q * (1.0f / DMODEL) + 1e-5f);
    float4 gv = ((const float4*)g)[tid];
    float4 bv = ((const float4*)bb)[tid];
    float4 o;
    o.x = dx * rs * gv.x + bv.x;
    o.y = dy * rs * gv.y + bv.y;
    o.z = dz * rs * gv.z + bv.z;
    o.w = dw * rs * gv.w + bv.w;
    xr4[tid] = o;
    float4 ot;
    ot.x = tf32r(o.x); ot.y = tf32r(o.y); ot.z = tf32r(o.z); ot.w = tf32r(o.w);
    ((float4*)(xt + off))[tid] = ot;
}

// ---------------- host orchestration ----------------------------------------
static inline GArg3 g1(const float* A, const float* W, const float* B, float* C,
                       int M) {
    GArg3 t;
    for (int i = 0; i < 3; i++) {
        t.A[i] = A; t.W[i] = W; t.Bi[i] = B; t.C[i] = C; t.M[i] = M;
    }
    return t;
}

extern "C" void kernel_launch(void* const* d_in, const int* in_sizes, int n_in,
                              void* d_out, int out_size) {
    (void)n_in; (void)out_size;
    int dict = (in_sizes[3] == 32768000);
    int base, iFCW, iFCB, iN1G, iN1B, iN2G, iN2B, iN3G, iN3B;
    if (dict) {
        iFCW = 3; iFCB = 4; base = 5;
        iN1G = base + 20; iN2G = base + 21; iN3G = base + 22;
        iN1B = base + 23; iN2B = base + 24; iN3B = base + 25;
    } else {
        base = 3; iFCW = 29; iFCB = 30;
        iN1G = base + 20; iN1B = base + 21; iN2G = base + 22;
        iN2B = base + 23; iN3G = base + 24; iN3B = base + 25;
    }
    const float* src  = (const float*)d_in[0];
    const int*   tgt  = (const int*)d_in[1];
    const float* emb  = (const float*)d_in[2];
    const float* fcw  = (const float*)d_in[iFCW];
    const float* fcb  = (const float*)d_in[iFCB];
    const float* AP[16];
    for (int i = 0; i < 16; i++) AP[i] = (const float*)d_in[base + i];
    const float* w1 = (const float*)d_in[base + 16];
    const float* b1 = (const float*)d_in[base + 17];
    const float* w2 = (const float*)d_in[base + 18];
    const float* b2 = (const float*)d_in[base + 19];
    const float* n1g = (const float*)d_in[iN1G];
    const float* n1b = (const float*)d_in[iN1B];
    const float* n2g = (const float*)d_in[iN2G];
    const float* n2b = (const float*)d_in[iN2B];
    const float* n3g = (const float*)d_in[iN3G];
    const float* n3b = (const float*)d_in[iN3B];

    float *x, *xt, *enc, *enct, *q, *k, *v, *attn, *proj, *ffn, *wt;
    cudaGetSymbolAddress((void**)&x,    g_x);
    cudaGetSymbolAddress((void**)&xt,   g_xt);
    cudaGetSymbolAddress((void**)&enc,  g_enc);
    cudaGetSymbolAddress((void**)&enct, g_enct);
    cudaGetSymbolAddress((void**)&q,    g_q);
    cudaGetSymbolAddress((void**)&k,    g_k);
    cudaGetSymbolAddress((void**)&v,    g_v);
    cudaGetSymbolAddress((void**)&attn, g_attn);
    cudaGetSymbolAddress((void**)&proj, g_proj);
    cudaGetSymbolAddress((void**)&ffn,  g_ffn);
    cudaGetSymbolAddress((void**)&wt,   g_wt);

    cudaFuncSetAttribute(gemm_tf32, cudaFuncAttributeMaxDynamicSharedMemorySize,
                         GEMM_SMEM);
    cudaFuncSetAttribute(flash_attn, cudaFuncAttributeMaxDynamicSharedMemorySize,
                         FLASH_SMEM);

    // ---- one-time weight pre-round into g_wt ----
    const int ATT_N4 = WT_ATTN_TENSOR / 4;            // 8M floats / 4
    for (int i = 0; i < 8; i++)
        cvt_tf32<<<(ATT_N4 + 255) / 256, 256>>>(
            AP[2 * i], wt + (size_t)i * WT_ATTN_TENSOR, ATT_N4);
    const int W1_N4 = NLAYER * DMODEL * DFF / 4;
    cvt_tf32<<<(W1_N4 + 255) / 256, 256>>>(w1, wt + WT_OFF_W1, W1_N4);
    cvt_tf32<<<(W1_N4 + 255) / 256, 256>>>(w2, wt + WT_OFF_W2, W1_N4);
    const int FC_N4 = DMODEL * VOC / 4;
    cvt_tf32<<<(FC_N4 + 255) / 256, 256>>>(fcw, wt + WT_OFF_FCW, FC_N4);

    encpe_kernel<<<NE, 256>>>(src, enc, enct);
    embed_kernel<<<NQ, 256>>>(tgt, emb, x, xt);

    dim3 gDD(DMODEL / BNt, NQ / BMt, 1);
    dim3 gDD3(DMODEL / BNt, NQ / BMt, 3);
    dim3 gFF(DFF / BNt, NQ / BMt, 1);

    const float* WT[8];
    for (int i = 0; i < 8; i++) WT[i] = wt + (size_t)i * WT_ATTN_TENSOR;
    const float* w1t = wt + WT_OFF_W1;
    const float* w2t = wt + WT_OFF_W2;
    const float* fcwt = wt + WT_OFF_FCW;

    for (int l = 0; l < NLAYER; l++) {
        size_t ow = (size_t)l * DMODEL * DMODEL, ob = (size_t)l * DMODEL;
        size_t ow1 = (size_t)l * DMODEL * DFF, ob1 = (size_t)l * DFF;

        // ---- self attention: batched QKV (outputs pre-rounded for flash) ----
        GArg3 qkv = g1(xt, WT[0] + ow, AP[1] + ob, q, NQ);
        qkv.W[1] = WT[1] + ow; qkv.Bi[1] = AP[3] + ob; qkv.C[1] = k;
        qkv.W[2] = WT[2] + ow; qkv.Bi[2] = AP[5] + ob; qkv.C[2] = v;
        gemm_tf32<<<gDD3, 256, GEMM_SMEM>>>(qkv, DMODEL, DMODEL, 0, 1);
        flash_attn<<<dim3(8, NHEAD, Bsz), 128, FLASH_SMEM>>>(q, k, v, attn,
                                                             TGTL, 1, tgt);
        gemm_tf32<<<gDD, 256, GEMM_SMEM>>>(
            g1(attn, WT[3] + ow, AP[7] + ob, proj, NQ), DMODEL, DMODEL, 0, 0);
        ln_res<<<NQ, 256>>>(x, proj, n1g + ob, n1b + ob, xt);

        // ---- cross attention: fused Q (on x) + K,V (on enc) ----
        GArg3 ckv = g1(xt, WT[4] + ow, AP[9] + ob, q, NQ);
        ckv.A[1] = enct; ckv.W[1] = WT[5] + ow; ckv.Bi[1] = AP[11] + ob; ckv.C[1] = k; ckv.M[1] = NE;
        ckv.A[2] = enct; ckv.W[2] = WT[6] + ow; ckv.Bi[2] = AP[13] + ob; ckv.C[2] = v; ckv.M[2] = NE;
        gemm_tf32<<<gDD3, 256, GEMM_SMEM>>>(ckv, DMODEL, DMODEL, 0, 1);
        flash_attn<<<dim3(8, NHEAD, Bsz), 128, FLASH_SMEM>>>(q, k, v, attn,
                                                             SRCL, 0, tgt);
        gemm_tf32<<<gDD, 256, GEMM_SMEM>>>(
            g1(attn, WT[7] + ow, AP[15] + ob, proj, NQ), DMODEL, DMODEL, 0, 0);
        ln_res<<<NQ, 256>>>(x, proj, n2g + ob, n2b + ob, xt);

        // ---- feed forward ----
        gemm_tf32<<<gFF, 256, GEMM_SMEM>>>(
            g1(xt, w1t + ow1, b1 + ob1, ffn, NQ), DFF, DMODEL, 1, 1);
        gemm_tf32<<<gDD, 256, GEMM_SMEM>>>(
            g1(ffn, w2t + ow1, b2 + ob, proj, NQ), DMODEL, DFF, 0, 0);
        ln_res<<<NQ, 256>>>(x, proj, n3g + ob, n3b + ob, xt);
    }

    // ---- final projection to vocab ----
    gemm_tf32<<<dim3(VOC / BNt, NQ / BMt, 1), 256, GEMM_SMEM>>>(
        g1(xt, fcwt, fcb, (float*)d_out, NQ), VOC, DMODEL, 0, 0);
}

// round 14
// speedup vs baseline: 1.5001x; 1.0026x over previous
#include <cuda_runtime.h>
#include <math.h>
#include <stdint.h>

#define Bsz 4
#define SRCL 256
#define TGTL 512
#define DMODEL 1024
#define NHEAD 16
#define DKH 64
#define NLAYER 8
#define DFF 4096
#define VOC 32000
#define NQ (Bsz*TGTL)
#define NE (Bsz*SRCL)

// ---------------- scratch (device globals; no allocations allowed) ----------
__device__ float g_x[NQ*DMODEL];
__device__ float g_enc[NE*DMODEL];
__device__ float g_q[NQ*DMODEL];
__device__ float g_k[NQ*DMODEL];
__device__ float g_v[NQ*DMODEL];
__device__ float g_attn[NQ*DMODEL];
__device__ float g_proj[NQ*DMODEL];
__device__ float g_ffn[NQ*DFF];

// ---------------- helpers ---------------------------------------------------
__device__ __forceinline__ float blkReduceSum(float v) {
    #pragma unroll
    for (int o = 16; o > 0; o >>= 1) v += __shfl_xor_sync(0xffffffffu, v, o);
    __shared__ float sm[8];
    int w = threadIdx.x >> 5, ln = threadIdx.x & 31;
    __syncthreads();
    if (ln == 0) sm[w] = v;
    __syncthreads();
    float r = sm[0];
    #pragma unroll
    for (int i = 1; i < 8; i++) r += sm[i];
    return r;
}

__device__ __forceinline__ uint32_t f2tf32(float f) {
    uint32_t u;
    asm("cvt.rna.tf32.f32 %0, %1;" : "=r"(u) : "f"(f));
    return u;
}

#define MMA_TF32(ACC, A0, A1, A2, A3, B0, B1)                                  \
    asm volatile(                                                              \
        "mma.sync.aligned.m16n8k8.row.col.f32.tf32.tf32.f32 "                  \
        "{%0,%1,%2,%3},{%4,%5,%6,%7},{%8,%9},{%0,%1,%2,%3};"                   \
        : "+f"((ACC)[0]), "+f"((ACC)[1]), "+f"((ACC)[2]), "+f"((ACC)[3])       \
        : "r"(A0), "r"(A1), "r"(A2), "r"(A3), "r"(B0), "r"(B1))

#define CP_ASYNC16(dst, src)                                                   \
    asm volatile("cp.async.ca.shared.global [%0], [%1], 16;" ::                \
                 "r"(dst), "l"(src))
#define CP_COMMIT() asm volatile("cp.async.commit_group;")
#define CP_WAIT2()  asm volatile("cp.async.wait_group 2;")

__device__ __forceinline__ float pe_val(int pos, int d) {
    float div = expf((float)(d & ~1) * (-9.210340371976184f / 1024.0f));
    float ang = (float)pos * div;
    return (d & 1) ? cosf(ang) : sinf(ang);
}

// ---------------- embedding / encoder PE ------------------------------------
__global__ void embed_kernel(const int* __restrict__ tgt,
                             const float* __restrict__ emb,
                             float* __restrict__ x) {
    int row = blockIdx.x;
    int t = row % TGTL;
    int tok = tgt[row];
    const float* er = emb + (size_t)tok * DMODEL;
    float* xr = x + (size_t)row * DMODEL;
    for (int d = threadIdx.x; d < DMODEL; d += blockDim.x)
        xr[d] = er[d] + pe_val(t, d);
}

__global__ void encpe_kernel(const float* __restrict__ src,
                             float* __restrict__ enc) {
    int row = blockIdx.x;
    int s = row % SRCL;
    const float* sr = src + (size_t)row * DMODEL;
    float* er = enc + (size_t)row * DMODEL;
    for (int d = threadIdx.x; d < DMODEL; d += blockDim.x)
        er[d] = sr[d] + pe_val(s, d);
}

// ---------------- TF32 GEMM: cp.async 4-stage pipeline, z-batched ------------
// BM=128 variant: 8 warps of 64x32.
#define BMt 128
#define BNt 128
#define BKt 16
#define NSTG 4
#define AS_STRIDE 2560
#define BS_BASE   10240
#define BS_STRIDE 2176
#define GEMM_SMEM ((BS_BASE + NSTG*BS_STRIDE) * 4)

struct GArg3 {
    const float* A[3];
    const float* W[3];
    const float* Bi[3];
    float* C[3];
    int M[3];
};

__global__ void __launch_bounds__(256, 2)
gemm_tf32(GArg3 a3, int N, int K, int relu) {
    int z = blockIdx.z;
    const float* __restrict__ A = a3.A[z];
    const float* __restrict__ W = a3.W[z];
    const float* __restrict__ bias = a3.Bi[z];
    float* __restrict__ C = a3.C[z];
    int M = a3.M[z];

    int m0 = blockIdx.y * BMt, n0 = blockIdx.x * BNt;
    if (m0 >= M) return;

    extern __shared__ float smf[];
    uint32_t smem_u32 = (uint32_t)__cvta_generic_to_shared(smf);

    int tid = threadIdx.x;
    int warp = tid >> 5, lane = tid & 31;
    int g = lane >> 2, c = lane & 3;
    int wm = (warp & 1) * 64, wn = (warp >> 1) * 32;

    int arow = tid >> 1, acl = (tid & 1) * 2;
    const float* Asrc = A + (size_t)(m0 + arow) * K + acl * 4;
    uint32_t Adst = smem_u32 + (arow * 20 + acl * 4) * 4;
    int brow = tid >> 4, bcl = (tid & 15) * 2;
    const float* Bsrc = W + (size_t)brow * N + n0 + bcl * 4;
    uint32_t Bdst = smem_u32 + (BS_BASE + brow * 136 + bcl * 4) * 4;

#define ISSUE_STAGE(S, K0)                                                     \
    do {                                                                       \
        uint32_t ad = Adst + (S) * (AS_STRIDE * 4);                            \
        const float* as = Asrc + (K0);                                         \
        CP_ASYNC16(ad, as);                                                    \
        CP_ASYNC16(ad + 16, as + 4);                                           \
        uint32_t bd = Bdst + (S) * (BS_STRIDE * 4);                            \
        const float* bs = Bsrc + (size_t)(K0) * N;                             \
        CP_ASYNC16(bd, bs);                                                    \
        CP_ASYNC16(bd + 16, bs + 4);                                           \
    } while (0)

    float acc[4][4][4] = {};

    int T = K / BKt;
    ISSUE_STAGE(0, 0); CP_COMMIT();
    ISSUE_STAGE(1, BKt); CP_COMMIT();
    ISSUE_STAGE(2, 2 * BKt); CP_COMMIT();

    for (int t = 0; t < T; t++) {
        CP_WAIT2();
        __syncthreads();
        if (t + 3 < T) ISSUE_STAGE((t + 3) & 3, (t + 3) * BKt);
        CP_COMMIT();

        const float* As = smf + (t & 3) * AS_STRIDE;
        const float* Bs = smf + BS_BASE + (t & 3) * BS_STRIDE;
        #pragma unroll
        for (int ks = 0; ks < 2; ks++) {
            int kb = ks * 8;
            uint32_t af[4][4], bf[4][2];
            #pragma unroll
            for (int im = 0; im < 4; im++) {
                int m = wm + im * 16 + g;
                af[im][0] = f2tf32(As[m * 20 + kb + c]);
                af[im][1] = f2tf32(As[(m + 8) * 20 + kb + c]);
                af[im][2] = f2tf32(As[m * 20 + kb + c + 4]);
                af[im][3] = f2tf32(As[(m + 8) * 20 + kb + c + 4]);
            }
            #pragma unroll
            for (int jn = 0; jn < 4; jn++) {
                int n = wn + jn * 8 + g;
                bf[jn][0] = f2tf32(Bs[(kb + c) * 136 + n]);
                bf[jn][1] = f2tf32(Bs[(kb + c + 4) * 136 + n]);
            }
            #pragma unroll
            for (int im = 0; im < 4; im++)
                #pragma unroll
                for (int jn = 0; jn < 4; jn++)
                    MMA_TF32(acc[im][jn], af[im][0], af[im][1], af[im][2],
                             af[im][3], bf[jn][0], bf[jn][1]);
        }
    }
#undef ISSUE_STAGE

    #pragma unroll
    for (int jn = 0; jn < 4; jn++) {
        int col = n0 + wn + jn * 8 + 2 * c;
        float b0v = __ldg(bias + col), b1v = __ldg(bias + col + 1);
        #pragma unroll
        for (int im = 0; im < 4; im++) {
            int row0 = m0 + wm + im * 16 + g;
            float v0 = acc[im][jn][0] + b0v;
            float v1 = acc[im][jn][1] + b1v;
            float v2 = acc[im][jn][2] + b0v;
            float v3 = acc[im][jn][3] + b1v;
            if (relu) {
                v0 = fmaxf(v0, 0.f); v1 = fmaxf(v1, 0.f);
                v2 = fmaxf(v2, 0.f); v3 = fmaxf(v3, 0.f);
            }
            *(float2*)(C + (size_t)row0 * N + col)       = make_float2(v0, v1);
            *(float2*)(C + (size_t)(row0 + 8) * N + col) = make_float2(v2, v3);
        }
    }
}

// ---------------- BM=64 GEMM variant for thin (128-tile) GEMMs ---------------
// 64x128 tile, 8 warps of 32x32, grid doubles -> 2 waves / 2 CTAs per SM.
#define AS64_STRIDE 1280                  // 64 rows * 20
#define BS64_BASE   (NSTG*AS64_STRIDE)    // 5120
#define GEMM64_SMEM ((BS64_BASE + NSTG*BS_STRIDE) * 4)   // 55296 bytes

__global__ void __launch_bounds__(256, 2)
gemm_tf32_m64(const float* __restrict__ A, const float* __restrict__ W,
              const float* __restrict__ bias, float* __restrict__ C,
              int N, int K, int relu) {
    int m0 = blockIdx.y * 64, n0 = blockIdx.x * BNt;

    extern __shared__ float smf[];
    uint32_t smem_u32 = (uint32_t)__cvta_generic_to_shared(smf);

    int tid = threadIdx.x;
    int warp = tid >> 5, lane = tid & 31;
    int g = lane >> 2, c = lane & 3;
    int wm = (warp & 1) * 32, wn = (warp >> 1) * 32;

    // A staging: 64 rows x 16 k; 4 threads/row, one float4 each
    int arow = tid >> 2, acl = tid & 3;
    const float* Asrc = A + (size_t)(m0 + arow) * K + acl * 4;
    uint32_t Adst = smem_u32 + (arow * 20 + acl * 4) * 4;
    // B staging: same as BM=128 kernel
    int brow = tid >> 4, bcl = (tid & 15) * 2;
    const float* Bsrc = W + (size_t)brow * N + n0 + bcl * 4;
    uint32_t Bdst = smem_u32 + (BS64_BASE + brow * 136 + bcl * 4) * 4;

#define ISSUE_STAGE64(S, K0)                                                   \
    do {                                                                       \
        CP_ASYNC16(Adst + (S) * (AS64_STRIDE * 4), Asrc + (K0));               \
        uint32_t bd = Bdst + (S) * (BS_STRIDE * 4);                            \
        const float* bs = Bsrc + (size_t)(K0) * N;                             \
        CP_ASYNC16(bd, bs);                                                    \
        CP_ASYNC16(bd + 16, bs + 4);                                           \
    } while (0)

    float acc[2][4][4] = {};

    int T = K / BKt;
    ISSUE_STAGE64(0, 0); CP_COMMIT();
    ISSUE_STAGE64(1, BKt); CP_COMMIT();
    ISSUE_STAGE64(2, 2 * BKt); CP_COMMIT();

    for (int t = 0; t < T; t++) {
        CP_WAIT2();
        __syncthreads();
        if (t + 3 < T) ISSUE_STAGE64((t + 3) & 3, (t + 3) * BKt);
        CP_COMMIT();

        const float* As = smf + (t & 3) * AS64_STRIDE;
        const float* Bs = smf + BS64_BASE + (t & 3) * BS_STRIDE;
        #pragma unroll
        for (int ks = 0; ks < 2; ks++) {
            int kb = ks * 8;
            uint32_t af[2][4], bf[4][2];
            #pragma unroll
            for (int im = 0; im < 2; im++) {
                int m = wm + im * 16 + g;
                af[im][0] = f2tf32(As[m * 20 + kb + c]);
                af[im][1] = f2tf32(As[(m + 8) * 20 + kb + c]);
                af[im][2] = f2tf32(As[m * 20 + kb + c + 4]);
                af[im][3] = f2tf32(As[(m + 8) * 20 + kb + c + 4]);
            }
            #pragma unroll
            for (int jn = 0; jn < 4; jn++) {
                int n = wn + jn * 8 + g;
                bf[jn][0] = f2tf32(Bs[(kb + c) * 136 + n]);
                bf[jn][1] = f2tf32(Bs[(kb + c + 4) * 136 + n]);
            }
            #pragma unroll
            for (int im = 0; im < 2; im++)
                #pragma unroll
                for (int jn = 0; jn < 4; jn++)
                    MMA_TF32(acc[im][jn], af[im][0], af[im][1], af[im][2],
                             af[im][3], bf[jn][0], bf[jn][1]);
        }
    }
#undef ISSUE_STAGE64

    #pragma unroll
    for (int jn = 0; jn < 4; jn++) {
        int col = n0 + wn + jn * 8 + 2 * c;
        float b0v = __ldg(bias + col), b1v = __ldg(bias + col + 1);
        #pragma unroll
        for (int im = 0; im < 2; im++) {
            int row0 = m0 + wm + im * 16 + g;
            float v0 = acc[im][jn][0] + b0v;
            float v1 = acc[im][jn][1] + b1v;
            float v2 = acc[im][jn][2] + b0v;
            float v3 = acc[im][jn][3] + b1v;
            if (relu) {
                v0 = fmaxf(v0, 0.f); v1 = fmaxf(v1, 0.f);
                v2 = fmaxf(v2, 0.f); v3 = fmaxf(v3, 0.f);
            }
            *(float2*)(C + (size_t)row0 * N + col)       = make_float2(v0, v1);
            *(float2*)(C + (size_t)(row0 + 8) * N + col) = make_float2(v2, v3);
        }
    }
}

// ---------------- fused flash attention --------------------------------------
#define FLASH_SMEM ((64*68*2 + 64*72) * 4)

__global__ void __launch_bounds__(128)
flash_attn(const float* __restrict__ Q, const float* __restrict__ Kg,
           const float* __restrict__ Vg, float* __restrict__ O,
           int Sk, int causal, const int* __restrict__ tgt) {
    extern __shared__ uint32_t sm_u[];
    uint32_t (*Qs)[68]  = (uint32_t(*)[68])sm_u;
    uint32_t (*KPs)[68] = (uint32_t(*)[68])(sm_u + 64 * 68);
    uint32_t (*Vs)[72]  = (uint32_t(*)[72])(sm_u + 2 * 64 * 68);

    int qt = blockIdx.x, h = blockIdx.y, b = blockIdx.z;
    int tid = threadIdx.x, warp = tid >> 5, lane = tid & 31;
    int g = lane >> 2, c = lane & 3;
    int row = tid >> 1, kg = (tid & 1) * 32;
    int mw = warp * 16;

    const float* qp = Q + (size_t)(b * TGTL + qt * 64 + row) * DMODEL + h * 64 + kg;
    #pragma unroll
    for (int u = 0; u < 8; u++) {
        float4 qv = *(const float4*)(qp + u * 4);
        int cc = kg + u * 4;
        Qs[row][cc + 0] = f2tf32(qv.x); Qs[row][cc + 1] = f2tf32(qv.y);
        Qs[row][cc + 2] = f2tf32(qv.z); Qs[row][cc + 3] = f2tf32(qv.w);
    }

    int gi0 = qt * 64 + mw + g, gi1 = gi0 + 8;
    int ok0 = 1, ok1 = 1;
    if (causal) {
        ok0 = (tgt[b * TGTL + gi0] != 0);
        ok1 = (tgt[b * TGTL + gi1] != 0);
    }

    float m0r = -1e30f, m1r = -1e30f, l0 = 0.f, l1 = 0.f;
    float o[8][4] = {};

    int nkt = Sk >> 6;
    for (int kt = 0; kt < nkt; kt++) {
        bool skipk = (causal != 0) && (kt > qt);
        __syncthreads();
        const float* vp = Vg + (size_t)(b * Sk + kt * 64 + row) * DMODEL + h * 64 + kg;
        if (!skipk) {
            const float* kp = Kg + (size_t)(b * Sk + kt * 64 + row) * DMODEL + h * 64 + kg;
            #pragma unroll
            for (int u = 0; u < 8; u++) {
                float4 kv = *(const float4*)(kp + u * 4);
                int cc = kg + u * 4;
                KPs[row][cc + 0] = f2tf32(kv.x); KPs[row][cc + 1] = f2tf32(kv.y);
                KPs[row][cc + 2] = f2tf32(kv.z); KPs[row][cc + 3] = f2tf32(kv.w);
            }
        }
        #pragma unroll
        for (int u = 0; u < 8; u++) {
            float4 vv = *(const float4*)(vp + u * 4);
            int cc = kg + u * 4;
            Vs[row][cc + 0] = f2tf32(vv.x); Vs[row][cc + 1] = f2tf32(vv.y);
            Vs[row][cc + 2] = f2tf32(vv.z); Vs[row][cc + 3] = f2tf32(vv.w);
        }
        __syncthreads();

        float s[8][4];
        if (!skipk) {
            #pragma unroll
            for (int nb = 0; nb < 8; nb++)
                s[nb][0] = s[nb][1] = s[nb][2] = s[nb][3] = 0.f;
            #pragma unroll
            for (int kb = 0; kb < 64; kb += 8) {
                uint32_t a0 = Qs[mw + g][kb + c];
                uint32_t a1 = Qs[mw + g + 8][kb + c];
                uint32_t a2 = Qs[mw + g][kb + c + 4];
                uint32_t a3 = Qs[mw + g + 8][kb + c + 4];
                #pragma unroll
                for (int nb = 0; nb < 8; nb++) {
                    uint32_t b0 = KPs[nb * 8 + g][kb + c];
                    uint32_t b1 = KPs[nb * 8 + g][kb + c + 4];
                    MMA_TF32(s[nb], a0, a1, a2, a3, b0, b1);
                }
            }
            #pragma unroll
            for (int nb = 0; nb < 8; nb++) {
                int gj = kt * 64 + nb * 8 + 2 * c;
                s[nb][0] *= 0.125f; s[nb][1] *= 0.125f;
                s[nb][2] *= 0.125f; s[nb][3] *= 0.125f;
                if (causal) {
                    if (gj > gi0 || !ok0)     s[nb][0] = -1e9f;
                    if (gj + 1 > gi0 || !ok0) s[nb][1] = -1e9f;
                    if (gj > gi1 || !ok1)     s[nb][2] = -1e9f;
                    if (gj + 1 > gi1 || !ok1) s[nb][3] = -1e9f;
                }
            }
        } else {
            #pragma unroll
            for (int nb = 0; nb < 8; nb++)
                s[nb][0] = s[nb][1] = s[nb][2] = s[nb][3] = -1e9f;
        }

        float t0 = -1e30f, t1 = -1e30f;
        #pragma unroll
        for (int nb = 0; nb < 8; nb++) {
            t0 = fmaxf(t0, fmaxf(s[nb][0], s[nb][1]));
            t1 = fmaxf(t1, fmaxf(s[nb][2], s[nb][3]));
        }
        t0 = fmaxf(t0, __shfl_xor_sync(0xffffffffu, t0, 1));
        t0 = fmaxf(t0, __shfl_xor_sync(0xffffffffu, t0, 2));
        t1 = fmaxf(t1, __shfl_xor_sync(0xffffffffu, t1, 1));
        t1 = fmaxf(t1, __shfl_xor_sync(0xffffffffu, t1, 2));
        float nm0 = fmaxf(m0r, t0), nm1 = fmaxf(m1r, t1);
        float f0 = __expf(m0r - nm0), f1 = __expf(m1r - nm1);
        float ts0 = 0.f, ts1 = 0.f;
        #pragma unroll
        for (int nb = 0; nb < 8; nb++) {
            s[nb][0] = __expf(s[nb][0] - nm0);
            s[nb][1] = __expf(s[nb][1] - nm0);
            s[nb][2] = __expf(s[nb][2] - nm1);
            s[nb][3] = __expf(s[nb][3] - nm1);
            ts0 += s[nb][0] + s[nb][1];
            ts1 += s[nb][2] + s[nb][3];
        }
        ts0 += __shfl_xor_sync(0xffffffffu, ts0, 1);
        ts0 += __shfl_xor_sync(0xffffffffu, ts0, 2);
        ts1 += __shfl_xor_sync(0xffffffffu, ts1, 1);
        ts1 += __shfl_xor_sync(0xffffffffu, ts1, 2);
        l0 = l0 * f0 + ts0;
        l1 = l1 * f1 + ts1;
        m0r = nm0; m1r = nm1;
        #pragma unroll
        for (int nb = 0; nb < 8; nb++) {
            o[nb][0] *= f0; o[nb][1] *= f0;
            o[nb][2] *= f1; o[nb][3] *= f1;
        }
        __syncthreads();
        #pragma unroll
        for (int nb = 0; nb < 8; nb++) {
            int cc = nb * 8 + 2 * c;
            KPs[mw + g][cc]     = f2tf32(s[nb][0]);
            KPs[mw + g][cc + 1] = f2tf32(s[nb][1]);
            KPs[mw + g + 8][cc]     = f2tf32(s[nb][2]);
            KPs[mw + g + 8][cc + 1] = f2tf32(s[nb][3]);
        }
        __syncthreads();
        #pragma unroll
        for (int kb = 0; kb < 64; kb += 8) {
            uint32_t a0 = KPs[mw + g][kb + c];
            uint32_t a1 = KPs[mw + g + 8][kb + c];
            uint32_t a2 = KPs[mw + g][kb + c + 4];
            uint32_t a3 = KPs[mw + g + 8][kb + c + 4];
            #pragma unroll
            for (int nb = 0; nb < 8; nb++) {
                uint32_t b0 = Vs[kb + c][nb * 8 + g];
                uint32_t b1 = Vs[kb + c + 4][nb * 8 + g];
                MMA_TF32(o[nb], a0, a1, a2, a3, b0, b1);
            }
        }
    }

    float inv0 = 1.0f / l0, inv1 = 1.0f / l1;
    #pragma unroll
    for (int nb = 0; nb < 8; nb++) {
        int col = h * 64 + nb * 8 + 2 * c;
        size_t r0 = (size_t)(b * TGTL + qt * 64 + mw + g);
        *(float2*)(O + r0 * DMODEL + col) =
            make_float2(o[nb][0] * inv0, o[nb][1] * inv0);
        *(float2*)(O + (r0 + 8) * DMODEL + col) =
            make_float2(o[nb][2] * inv1, o[nb][3] * inv1);
    }
}

// ---------------- fused residual + LayerNorm (x = LN(x + a)) ----------------
__global__ void ln_res(float* __restrict__ x, const float* __restrict__ a,
                       const float* __restrict__ g, const float* __restrict__ bb) {
    int row = blockIdx.x, tid = threadIdx.x;
    float4* xr4 = (float4*)(x + (size_t)row * DMODEL);
    const float4* ar4 = (const float4*)(a + (size_t)row * DMODEL);
    float4 v = xr4[tid];
    float4 av = ar4[tid];
    v.x += av.x; v.y += av.y; v.z += av.z; v.w += av.w;
    float s = v.x + v.y + v.z + v.w;
    s = blkReduceSum(s);
    float mu = s * (1.0f / DMODEL);
    float dx = v.x - mu, dy = v.y - mu, dz = v.z - mu, dw = v.w - mu;
    float q = dx * dx + dy * dy + dz * dz + dw * dw;
    q = blkReduceSum(q);
    float rs = rsqrtf(q * (1.0f / DMODEL) + 1e-5f);
    float4 gv = ((const float4*)g)[tid];
    float4 bv = ((const float4*)bb)[tid];
    float4 o;
    o.x = dx * rs * gv.x + bv.x;
    o.y = dy * rs * gv.y + bv.y;
    o.z = dz * rs * gv.z + bv.z;
    o.w = dw * rs * gv.w + bv.w;
    xr4[tid] = o;
}

// ---------------- host orchestration ----------------------------------------
static inline GArg3 g1(const float* A, const float* W, const float* B, float* C,
                       int M) {
    GArg3 t;
    for (int i = 0; i < 3; i++) {
        t.A[i] = A; t.W[i] = W; t.Bi[i] = B; t.C[i] = C; t.M[i] = M;
    }
    return t;
}

extern "C" void kernel_launch(void* const* d_in, const int* in_sizes, int n_in,
                              void* d_out, int out_size) {
    (void)n_in; (void)out_size;
    int dict = (in_sizes[3] == 32768000);
    int base, iFCW, iFCB, iN1G, iN1B, iN2G, iN2B, iN3G, iN3B;
    if (dict) {
        iFCW = 3; iFCB = 4; base = 5;
        iN1G = base + 20; iN2G = base + 21; iN3G = base + 22;
        iN1B = base + 23; iN2B = base + 24; iN3B = base + 25;
    } else {
        base = 3; iFCW = 29; iFCB = 30;
        iN1G = base + 20; iN1B = base + 21; iN2G = base + 22;
        iN2B = base + 23; iN3G = base + 24; iN3B = base + 25;
    }
    const float* src  = (const float*)d_in[0];
    const int*   tgt  = (const int*)d_in[1];
    const float* emb  = (const float*)d_in[2];
    const float* fcw  = (const float*)d_in[iFCW];
    const float* fcb  = (const float*)d_in[iFCB];
    const float* AP[16];
    for (int i = 0; i < 16; i++) AP[i] = (const float*)d_in[base + i];
    const float* w1 = (const float*)d_in[base + 16];
    const float* b1 = (const float*)d_in[base + 17];
    const float* w2 = (const float*)d_in[base + 18];
    const float* b2 = (const float*)d_in[base + 19];
    const float* n1g = (const float*)d_in[iN1G];
    const float* n1b = (const float*)d_in[iN1B];
    const float* n2g = (const float*)d_in[iN2G];
    const float* n2b = (const float*)d_in[iN2B];
    const float* n3g = (const float*)d_in[iN3G];
    const float* n3b = (const float*)d_in[iN3B];

    float *x, *enc, *q, *k, *v, *attn, *proj, *ffn;
    cudaGetSymbolAddress((void**)&x,    g_x);
    cudaGetSymbolAddress((void**)&enc,  g_enc);
    cudaGetSymbolAddress((void**)&q,    g_q);
    cudaGetSymbolAddress((void**)&k,    g_k);
    cudaGetSymbolAddress((void**)&v,    g_v);
    cudaGetSymbolAddress((void**)&attn, g_attn);
    cudaGetSymbolAddress((void**)&proj, g_proj);
    cudaGetSymbolAddress((void**)&ffn,  g_ffn);

    cudaFuncSetAttribute(gemm_tf32, cudaFuncAttributeMaxDynamicSharedMemorySize,
                         GEMM_SMEM);
    cudaFuncSetAttribute(gemm_tf32_m64,
                         cudaFuncAttributeMaxDynamicSharedMemorySize,
                         GEMM64_SMEM);
    cudaFuncSetAttribute(flash_attn, cudaFuncAttributeMaxDynamicSharedMemorySize,
                         FLASH_SMEM);

    encpe_kernel<<<NE, 256>>>(src, enc);
    embed_kernel<<<NQ, 256>>>(tgt, emb, x);

    dim3 gDD3(DMODEL / BNt, NQ / BMt, 3);       // batched QKV / cross QKV
    dim3 gThin(DMODEL / BNt, NQ / 64, 1);       // 8 x 32 = 256 CTAs (BM=64)
    dim3 gFF(DFF / BNt, NQ / BMt, 1);           // 32 x 16

    for (int l = 0; l < NLAYER; l++) {
        size_t ow = (size_t)l * DMODEL * DMODEL, ob = (size_t)l * DMODEL;
        size_t ow1 = (size_t)l * DMODEL * DFF, ob1 = (size_t)l * DFF;

        // ---- self attention: batched QKV ----
        GArg3 qkv = g1(x, AP[0] + ow, AP[1] + ob, q, NQ);
        qkv.W[1] = AP[2] + ow; qkv.Bi[1] = AP[3] + ob; qkv.C[1] = k;
        qkv.W[2] = AP[4] + ow; qkv.Bi[2] = AP[5] + ob; qkv.C[2] = v;
        gemm_tf32<<<gDD3, 256, GEMM_SMEM>>>(qkv, DMODEL, DMODEL, 0);
        flash_attn<<<dim3(8, NHEAD, Bsz), 128, FLASH_SMEM>>>(q, k, v, attn,
                                                             TGTL, 1, tgt);
        gemm_tf32_m64<<<gThin, 256, GEMM64_SMEM>>>(
            attn, AP[6] + ow, AP[7] + ob, proj, DMODEL, DMODEL, 0);
        ln_res<<<NQ, 256>>>(x, proj, n1g + ob, n1b + ob);

        // ---- cross attention: fused Q (on x) + K,V (on enc) ----
        GArg3 ckv = g1(x, AP[8] + ow, AP[9] + ob, q, NQ);
        ckv.A[1] = enc; ckv.W[1] = AP[10] + ow; ckv.Bi[1] = AP[11] + ob; ckv.C[1] = k; ckv.M[1] = NE;
        ckv.A[2] = enc; ckv.W[2] = AP[12] + ow; ckv.Bi[2] = AP[13] + ob; ckv.C[2] = v; ckv.M[2] = NE;
        gemm_tf32<<<gDD3, 256, GEMM_SMEM>>>(ckv, DMODEL, DMODEL, 0);
        flash_attn<<<dim3(8, NHEAD, Bsz), 128, FLASH_SMEM>>>(q, k, v, attn,
                                                             SRCL, 0, tgt);
        gemm_tf32_m64<<<gThin, 256, GEMM64_SMEM>>>(
            attn, AP[14] + ow, AP[15] + ob, proj, DMODEL, DMODEL, 0);
        ln_res<<<NQ, 256>>>(x, proj, n2g + ob, n2b + ob);

        // ---- feed forward ----
        gemm_tf32<<<gFF, 256, GEMM_SMEM>>>(
            g1(x, w1 + ow1, b1 + ob1, ffn, NQ), DFF, DMODEL, 1);
        gemm_tf32_m64<<<gThin, 256, GEMM64_SMEM>>>(
            ffn, w2 + ow1, b2 + ob, proj, DMODEL, DFF, 0);
        ln_res<<<NQ, 256>>>(x, proj, n3g + ob, n3b + ob);
    }

    // ---- final projection to vocab ----
    gemm_tf32<<<dim3(VOC / BNt, NQ / BMt, 1), 256, GEMM_SMEM>>>(
        g1(x, fcw, fcb, (float*)d_out, NQ), VOC, DMODEL, 0);
}

// round 16
// speedup vs baseline: 1.8724x; 1.2482x over previous
#include <cuda_runtime.h>
#include <cuda_fp16.h>
#include <math.h>
#include <stdint.h>

#define Bsz 4
#define SRCL 256
#define TGTL 512
#define DMODEL 1024
#define NHEAD 16
#define DKH 64
#define NLAYER 8
#define DFF 4096
#define VOC 32000
#define NQ (Bsz*TGTL)
#define NE (Bsz*SRCL)

// weight-scratch offsets (halfs) — transposed [N][K] fp16 weights
#define WT_ATTN_TENSOR (NLAYER*DMODEL*DMODEL)
#define WT_OFF_W1   (8u*WT_ATTN_TENSOR)
#define WT_OFF_W2   (WT_OFF_W1 + NLAYER*DMODEL*DFF)
#define WT_OFF_FCW  (WT_OFF_W2 + NLAYER*DFF*DMODEL)
#define WT_TOTAL    (WT_OFF_FCW + DMODEL*VOC)

// ---------------- scratch (device globals; no allocations allowed) ----------
__device__ float g_x[NQ*DMODEL];
__device__ float g_enc[NE*DMODEL];
__device__ float g_q[NQ*DMODEL];
__device__ float g_k[NQ*DMODEL];
__device__ float g_v[NQ*DMODEL];
__device__ float g_attn[NQ*DMODEL];
__device__ float g_proj[NQ*DMODEL];
__device__ float g_ffn[NQ*DFF];
__device__ __half g_wh[WT_TOTAL];

// ---------------- helpers ---------------------------------------------------
__device__ __forceinline__ float blkReduceSum(float v) {
    #pragma unroll
    for (int o = 16; o > 0; o >>= 1) v += __shfl_xor_sync(0xffffffffu, v, o);
    __shared__ float sm[8];
    int w = threadIdx.x >> 5, ln = threadIdx.x & 31;
    __syncthreads();
    if (ln == 0) sm[w] = v;
    __syncthreads();
    float r = sm[0];
    #pragma unroll
    for (int i = 1; i < 8; i++) r += sm[i];
    return r;
}

__device__ __forceinline__ uint32_t f2tf32(float f) {
    uint32_t u;
    asm("cvt.rna.tf32.f32 %0, %1;" : "=r"(u) : "f"(f));
    return u;
}

__device__ __forceinline__ uint32_t pack_h2(float a, float b) {
    __half2 h = __floats2half2_rn(a, b);
    return *(uint32_t*)&h;
}

#define MMA_TF32(ACC, A0, A1, A2, A3, B0, B1)                                  \
    asm volatile(                                                              \
        "mma.sync.aligned.m16n8k8.row.col.f32.tf32.tf32.f32 "                  \
        "{%0,%1,%2,%3},{%4,%5,%6,%7},{%8,%9},{%0,%1,%2,%3};"                   \
        : "+f"((ACC)[0]), "+f"((ACC)[1]), "+f"((ACC)[2]), "+f"((ACC)[3])       \
        : "r"(A0), "r"(A1), "r"(A2), "r"(A3), "r"(B0), "r"(B1))

#define MMA_F16(ACC, A0, A1, A2, A3, B0, B1)                                   \
    asm volatile(                                                              \
        "mma.sync.aligned.m16n8k16.row.col.f32.f16.f16.f32 "                   \
        "{%0,%1,%2,%3},{%4,%5,%6,%7},{%8,%9},{%0,%1,%2,%3};"                   \
        : "+f"((ACC)[0]), "+f"((ACC)[1]), "+f"((ACC)[2]), "+f"((ACC)[3])       \
        : "r"(A0), "r"(A1), "r"(A2), "r"(A3), "r"(B0), "r"(B1))

__device__ __forceinline__ float pe_val(int pos, int d) {
    float div = expf((float)(d & ~1) * (-9.210340371976184f / 1024.0f));
    float ang = (float)pos * div;
    return (d & 1) ? cosf(ang) : sinf(ang);
}

// ---------------- weight transpose + fp16 convert: Wh[n][k] = h(W[k][n]) ----
__global__ void transpose_w(const float* __restrict__ W, __half* __restrict__ Wh,
                            int K, int N) {
    __shared__ float t[32][33];
    size_t zoff = (size_t)blockIdx.z * (size_t)K * N;
    int kb = blockIdx.y * 32, nb = blockIdx.x * 32;
    int tx = threadIdx.x, ty = threadIdx.y;   // 32 x 8
    #pragma unroll
    for (int i = 0; i < 32; i += 8)
        t[ty + i][tx] = W[zoff + (size_t)(kb + ty + i) * N + nb + tx];
    __syncthreads();
    #pragma unroll
    for (int i = 0; i < 32; i += 8)
        Wh[zoff + (size_t)(nb + ty + i) * K + kb + tx] = __float2half_rn(t[tx][ty + i]);
}

// ---------------- embedding / encoder PE ------------------------------------
__global__ void embed_kernel(const int* __restrict__ tgt,
                             const float* __restrict__ emb,
                             float* __restrict__ x) {
    int row = blockIdx.x;
    int t = row % TGTL;
    int tok = tgt[row];
    const float* er = emb + (size_t)tok * DMODEL;
    float* xr = x + (size_t)row * DMODEL;
    for (int d = threadIdx.x; d < DMODEL; d += blockDim.x)
        xr[d] = er[d] + pe_val(t, d);
}

__global__ void encpe_kernel(const float* __restrict__ src,
                             float* __restrict__ enc) {
    int row = blockIdx.x;
    int s = row % SRCL;
    const float* sr = src + (size_t)row * DMODEL;
    float* er = enc + (size_t)row * DMODEL;
    for (int d = threadIdx.x; d < DMODEL; d += blockDim.x)
        er[d] = sr[d] + pe_val(s, d);
}

// ---------------- FP16 tensor-core GEMM (z-batched) --------------------------
// C[M,N] = A[M,K](fp32, cvt at staging) @ Wh[N][K](fp16)^T + bias, opt relu.
// 128x128 tile, BK=16, 256 threads = 8 warps each 64x32.
// mma.m16n8k16.f16 -> 16 MMAs per warp per k-tile (vs 32 for tf32 k8).
// Smem rows of 12 words (8 used + 4 pad): fragment reads conflict-free.
#define BMt 128
#define BNt 128
#define BKt 16
#define ROWW 12           // words per smem row

struct GArg3 {
    const float* A[3];
    const __half* W[3];
    const float* Bi[3];
    float* C[3];
    int M[3];
};

__global__ void __launch_bounds__(256, 2)
gemm_f16(GArg3 a3, int N, int K, int relu) {
    int z = blockIdx.z;
    const float* __restrict__ A = a3.A[z];
    const __half* __restrict__ W = a3.W[z];
    const float* __restrict__ bias = a3.Bi[z];
    float* __restrict__ C = a3.C[z];
    int M = a3.M[z];

    int m0 = blockIdx.y * BMt, n0 = blockIdx.x * BNt;
    if (m0 >= M) return;

    __shared__ __align__(16) uint32_t As[2][BMt * ROWW];
    __shared__ __align__(16) uint32_t Bs[2][BNt * ROWW];

    int tid = threadIdx.x;
    int warp = tid >> 5, lane = tid & 31;
    int g = lane >> 2, c = lane & 3;
    int wm = (warp & 1) * 64, wn = (warp >> 1) * 32;

    // staging: row = tid>>1 (2 threads/row), hp = tid&1 covers k hp*8..hp*8+7
    int srow = tid >> 1, hp = tid & 1;
    const float* Asrc = A + (size_t)(m0 + srow) * K + hp * 8;
    const __half* Bsrc = W + (size_t)(n0 + srow) * K + hp * 8;
    int sword = srow * ROWW + hp * 4;

    float4 ra0, ra1;
    uint4 rb;
    ra0 = *(const float4*)(Asrc);
    ra1 = *(const float4*)(Asrc + 4);
    rb = *(const uint4*)(Bsrc);

#define STORE_STAGE(S)                                                         \
    do {                                                                       \
        uint4 aw;                                                              \
        aw.x = pack_h2(ra0.x, ra0.y);                                          \
        aw.y = pack_h2(ra0.z, ra0.w);                                          \
        aw.z = pack_h2(ra1.x, ra1.y);                                          \
        aw.w = pack_h2(ra1.z, ra1.w);                                          \
        *(uint4*)&As[S][sword] = aw;                                           \
        *(uint4*)&Bs[S][sword] = rb;                                           \
    } while (0)

    float acc[4][4][4] = {};

    STORE_STAGE(0);
    int T = K / BKt;
    for (int t = 0; t < T; t++) {
        __syncthreads();
        int s = t & 1;
        bool more = (t + 1 < T);
        if (more) {
            int k0 = (t + 1) * BKt;
            ra0 = *(const float4*)(Asrc + k0);
            ra1 = *(const float4*)(Asrc + k0 + 4);
            rb = *(const uint4*)(Bsrc + k0);
        }
        const uint32_t* As_ = As[s];
        const uint32_t* Bs_ = Bs[s];
        uint32_t af[4][4], bf[4][2];
        #pragma unroll
        for (int im = 0; im < 4; im++) {
            int m = wm + im * 16 + g;
            af[im][0] = As_[m * ROWW + c];
            af[im][1] = As_[(m + 8) * ROWW + c];
            af[im][2] = As_[m * ROWW + c + 4];
            af[im][3] = As_[(m + 8) * ROWW + c + 4];
        }
        #pragma unroll
        for (int jn = 0; jn < 4; jn++) {
            int n = wn + jn * 8 + g;
            bf[jn][0] = Bs_[n * ROWW + c];
            bf[jn][1] = Bs_[n * ROWW + c + 4];
        }
        #pragma unroll
        for (int im = 0; im < 4; im++)
            #pragma unroll
            for (int jn = 0; jn < 4; jn++)
                MMA_F16(acc[im][jn], af[im][0], af[im][1], af[im][2],
                        af[im][3], bf[jn][0], bf[jn][1]);
        if (more) STORE_STAGE(s ^ 1);
    }
#undef STORE_STAGE

    #pragma unroll
    for (int jn = 0; jn < 4; jn++) {
        int col = n0 + wn + jn * 8 + 2 * c;
        float b0v = __ldg(bias + col), b1v = __ldg(bias + col + 1);
        #pragma unroll
        for (int im = 0; im < 4; im++) {
            int row0 = m0 + wm + im * 16 + g;
            float v0 = acc[im][jn][0] + b0v;
            float v1 = acc[im][jn][1] + b1v;
            float v2 = acc[im][jn][2] + b0v;
            float v3 = acc[im][jn][3] + b1v;
            if (relu) {
                v0 = fmaxf(v0, 0.f); v1 = fmaxf(v1, 0.f);
                v2 = fmaxf(v2, 0.f); v3 = fmaxf(v3, 0.f);
            }
            *(float2*)(C + (size_t)row0 * N + col)       = make_float2(v0, v1);
            *(float2*)(C + (size_t)(row0 + 8) * N + col) = make_float2(v2, v3);
        }
    }
}

// ---------------- fused flash attention (tf32, unchanged from 7.66ms best) ---
#define FLASH_SMEM ((64*68*2 + 64*72) * 4)

__global__ void __launch_bounds__(128)
flash_attn(const float* __restrict__ Q, const float* __restrict__ Kg,
           const float* __restrict__ Vg, float* __restrict__ O,
           int Sk, int causal, const int* __restrict__ tgt) {
    extern __shared__ uint32_t sm_u[];
    uint32_t (*Qs)[68]  = (uint32_t(*)[68])sm_u;
    uint32_t (*KPs)[68] = (uint32_t(*)[68])(sm_u + 64 * 68);
    uint32_t (*Vs)[72]  = (uint32_t(*)[72])(sm_u + 2 * 64 * 68);

    int qt = blockIdx.x, h = blockIdx.y, b = blockIdx.z;
    int tid = threadIdx.x, warp = tid >> 5, lane = tid & 31;
    int g = lane >> 2, c = lane & 3;
    int row = tid >> 1, kg = (tid & 1) * 32;
    int mw = warp * 16;

    const float* qp = Q + (size_t)(b * TGTL + qt * 64 + row) * DMODEL + h * 64 + kg;
    #pragma unroll
    for (int u = 0; u < 8; u++) {
        float4 qv = *(const float4*)(qp + u * 4);
        int cc = kg + u * 4;
        Qs[row][cc + 0] = f2tf32(qv.x); Qs[row][cc + 1] = f2tf32(qv.y);
        Qs[row][cc + 2] = f2tf32(qv.z); Qs[row][cc + 3] = f2tf32(qv.w);
    }

    int gi0 = qt * 64 + mw + g, gi1 = gi0 + 8;
    int ok0 = 1, ok1 = 1;
    if (causal) {
        ok0 = (tgt[b * TGTL + gi0] != 0);
        ok1 = (tgt[b * TGTL + gi1] != 0);
    }

    float m0r = -1e30f, m1r = -1e30f, l0 = 0.f, l1 = 0.f;
    float o[8][4] = {};

    int nkt = Sk >> 6;
    for (int kt = 0; kt < nkt; kt++) {
        bool skipk = (causal != 0) && (kt > qt);
        __syncthreads();
        const float* vp = Vg + (size_t)(b * Sk + kt * 64 + row) * DMODEL + h * 64 + kg;
        if (!skipk) {
            const float* kp = Kg + (size_t)(b * Sk + kt * 64 + row) * DMODEL + h * 64 + kg;
            #pragma unroll
            for (int u = 0; u < 8; u++) {
                float4 kv = *(const float4*)(kp + u * 4);
                int cc = kg + u * 4;
                KPs[row][cc + 0] = f2tf32(kv.x); KPs[row][cc + 1] = f2tf32(kv.y);
                KPs[row][cc + 2] = f2tf32(kv.z); KPs[row][cc + 3] = f2tf32(kv.w);
            }
        }
        #pragma unroll
        for (int u = 0; u < 8; u++) {
            float4 vv = *(const float4*)(vp + u * 4);
            int cc = kg + u * 4;
            Vs[row][cc + 0] = f2tf32(vv.x); Vs[row][cc + 1] = f2tf32(vv.y);
            Vs[row][cc + 2] = f2tf32(vv.z); Vs[row][cc + 3] = f2tf32(vv.w);
        }
        __syncthreads();

        float s[8][4];
        if (!skipk) {
            #pragma unroll
            for (int nb = 0; nb < 8; nb++)
                s[nb][0] = s[nb][1] = s[nb][2] = s[nb][3] = 0.f;
            #pragma unroll
            for (int kb = 0; kb < 64; kb += 8) {
                uint32_t a0 = Qs[mw + g][kb + c];
                uint32_t a1 = Qs[mw + g + 8][kb + c];
                uint32_t a2 = Qs[mw + g][kb + c + 4];
                uint32_t a3 = Qs[mw + g + 8][kb + c + 4];
                #pragma unroll
                for (int nb = 0; nb < 8; nb++) {
                    uint32_t b0 = KPs[nb * 8 + g][kb + c];
                    uint32_t b1 = KPs[nb * 8 + g][kb + c + 4];
                    MMA_TF32(s[nb], a0, a1, a2, a3, b0, b1);
                }
            }
            #pragma unroll
            for (int nb = 0; nb < 8; nb++) {
                int gj = kt * 64 + nb * 8 + 2 * c;
                s[nb][0] *= 0.125f; s[nb][1] *= 0.125f;
                s[nb][2] *= 0.125f; s[nb][3] *= 0.125f;
                if (causal) {
                    if (gj > gi0 || !ok0)     s[nb][0] = -1e9f;
                    if (gj + 1 > gi0 || !ok0) s[nb][1] = -1e9f;
                    if (gj > gi1 || !ok1)     s[nb][2] = -1e9f;
                    if (gj + 1 > gi1 || !ok1) s[nb][3] = -1e9f;
                }
            }
        } else {
            #pragma unroll
            for (int nb = 0; nb < 8; nb++)
                s[nb][0] = s[nb][1] = s[nb][2] = s[nb][3] = -1e9f;
        }

        float t0 = -1e30f, t1 = -1e30f;
        #pragma unroll
        for (int nb = 0; nb < 8; nb++) {
            t0 = fmaxf(t0, fmaxf(s[nb][0], s[nb][1]));
            t1 = fmaxf(t1, fmaxf(s[nb][2], s[nb][3]));
        }
        t0 = fmaxf(t0, __shfl_xor_sync(0xffffffffu, t0, 1));
        t0 = fmaxf(t0, __shfl_xor_sync(0xffffffffu, t0, 2));
        t1 = fmaxf(t1, __shfl_xor_sync(0xffffffffu, t1, 1));
        t1 = fmaxf(t1, __shfl_xor_sync(0xffffffffu, t1, 2));
        float nm0 = fmaxf(m0r, t0), nm1 = fmaxf(m1r, t1);
        float f0 = __expf(m0r - nm0), f1 = __expf(m1r - nm1);
        float ts0 = 0.f, ts1 = 0.f;
        #pragma unroll
        for (int nb = 0; nb < 8; nb++) {
            s[nb][0] = __expf(s[nb][0] - nm0);
            s[nb][1] = __expf(s[nb][1] - nm0);
            s[nb][2] = __expf(s[nb][2] - nm1);
            s[nb][3] = __expf(s[nb][3] - nm1);
            ts0 += s[nb][0] + s[nb][1];
            ts1 += s[nb][2] + s[nb][3];
        }
        ts0 += __shfl_xor_sync(0xffffffffu, ts0, 1);
        ts0 += __shfl_xor_sync(0xffffffffu, ts0, 2);
        ts1 += __shfl_xor_sync(0xffffffffu, ts1, 1);
        ts1 += __shfl_xor_sync(0xffffffffu, ts1, 2);
        l0 = l0 * f0 + ts0;
        l1 = l1 * f1 + ts1;
        m0r = nm0; m1r = nm1;
        #pragma unroll
        for (int nb = 0; nb < 8; nb++) {
            o[nb][0] *= f0; o[nb][1] *= f0;
            o[nb][2] *= f1; o[nb][3] *= f1;
        }
        __syncthreads();
        #pragma unroll
        for (int nb = 0; nb < 8; nb++) {
            int cc = nb * 8 + 2 * c;
            KPs[mw + g][cc]     = f2tf32(s[nb][0]);
            KPs[mw + g][cc + 1] = f2tf32(s[nb][1]);
            KPs[mw + g + 8][cc]     = f2tf32(s[nb][2]);
            KPs[mw + g + 8][cc + 1] = f2tf32(s[nb][3]);
        }
        __syncthreads();
        #pragma unroll
        for (int kb = 0; kb < 64; kb += 8) {
            uint32_t a0 = KPs[mw + g][kb + c];
            uint32_t a1 = KPs[mw + g + 8][kb + c];
            uint32_t a2 = KPs[mw + g][kb + c + 4];
            uint32_t a3 = KPs[mw + g + 8][kb + c + 4];
            #pragma unroll
            for (int nb = 0; nb < 8; nb++) {
                uint32_t b0 = Vs[kb + c][nb * 8 + g];
                uint32_t b1 = Vs[kb + c + 4][nb * 8 + g];
                MMA_TF32(o[nb], a0, a1, a2, a3, b0, b1);
            }
        }
    }

    float inv0 = 1.0f / l0, inv1 = 1.0f / l1;
    #pragma unroll
    for (int nb = 0; nb < 8; nb++) {
        int col = h * 64 + nb * 8 + 2 * c;
        size_t r0 = (size_t)(b * TGTL + qt * 64 + mw + g);
        *(float2*)(O + r0 * DMODEL + col) =
            make_float2(o[nb][0] * inv0, o[nb][1] * inv0);
        *(float2*)(O + (r0 + 8) * DMODEL + col) =
            make_float2(o[nb][2] * inv1, o[nb][3] * inv1);
    }
}

// ---------------- fused residual + LayerNorm (x = LN(x + a)) ----------------
__global__ void ln_res(float* __restrict__ x, const float* __restrict__ a,
                       const float* __restrict__ g, const float* __restrict__ bb) {
    int row = blockIdx.x, tid = threadIdx.x;
    float4* xr4 = (float4*)(x + (size_t)row * DMODEL);
    const float4* ar4 = (const float4*)(a + (size_t)row * DMODEL);
    float4 v = xr4[tid];
    float4 av = ar4[tid];
    v.x += av.x; v.y += av.y; v.z += av.z; v.w += av.w;
    float s = v.x + v.y + v.z + v.w;
    s = blkReduceSum(s);
    float mu = s * (1.0f / DMODEL);
    float dx = v.x - mu, dy = v.y - mu, dz = v.z - mu, dw = v.w - mu;
    float q = dx * dx + dy * dy + dz * dz + dw * dw;
    q = blkReduceSum(q);
    float rs = rsqrtf(q * (1.0f / DMODEL) + 1e-5f);
    float4 gv = ((const float4*)g)[tid];
    float4 bv = ((const float4*)bb)[tid];
    float4 o;
    o.x = dx * rs * gv.x + bv.x;
    o.y = dy * rs * gv.y + bv.y;
    o.z = dz * rs * gv.z + bv.z;
    o.w = dw * rs * gv.w + bv.w;
    xr4[tid] = o;
}

// ---------------- host orchestration ----------------------------------------
static inline GArg3 g1(const float* A, const __half* W, const float* B,
                       float* C, int M) {
    GArg3 t;
    for (int i = 0; i < 3; i++) {
        t.A[i] = A; t.W[i] = W; t.Bi[i] = B; t.C[i] = C; t.M[i] = M;
    }
    return t;
}

extern "C" void kernel_launch(void* const* d_in, const int* in_sizes, int n_in,
                              void* d_out, int out_size) {
    (void)n_in; (void)out_size;
    int dict = (in_sizes[3] == 32768000);
    int base, iFCW, iFCB, iN1G, iN1B, iN2G, iN2B, iN3G, iN3B;
    if (dict) {
        iFCW = 3; iFCB = 4; base = 5;
        iN1G = base + 20; iN2G = base + 21; iN3G = base + 22;
        iN1B = base + 23; iN2B = base + 24; iN3B = base + 25;
    } else {
        base = 3; iFCW = 29; iFCB = 30;
        iN1G = base + 20; iN1B = base + 21; iN2G = base + 22;
        iN2B = base + 23; iN3G = base + 24; iN3B = base + 25;
    }
    const float* src  = (const float*)d_in[0];
    const int*   tgt  = (const int*)d_in[1];
    const float* emb  = (const float*)d_in[2];
    const float* fcw  = (const float*)d_in[iFCW];
    const float* fcb  = (const float*)d_in[iFCB];
    const float* AP[16];
    for (int i = 0; i < 16; i++) AP[i] = (const float*)d_in[base + i];
    const float* w1 = (const float*)d_in[base + 16];
    const float* b1 = (const float*)d_in[base + 17];
    const float* w2 = (const float*)d_in[base + 18];
    const float* b2 = (const float*)d_in[base + 19];
    const float* n1g = (const float*)d_in[iN1G];
    const float* n1b = (const float*)d_in[iN1B];
    const float* n2g = (const float*)d_in[iN2G];
    const float* n2b = (const float*)d_in[iN2B];
    const float* n3g = (const float*)d_in[iN3G];
    const float* n3b = (const float*)d_in[iN3B];

    float *x, *enc, *q, *k, *v, *attn, *proj, *ffn;
    __half* wh;
    cudaGetSymbolAddress((void**)&x,    g_x);
    cudaGetSymbolAddress((void**)&enc,  g_enc);
    cudaGetSymbolAddress((void**)&q,    g_q);
    cudaGetSymbolAddress((void**)&k,    g_k);
    cudaGetSymbolAddress((void**)&v,    g_v);
    cudaGetSymbolAddress((void**)&attn, g_attn);
    cudaGetSymbolAddress((void**)&proj, g_proj);
    cudaGetSymbolAddress((void**)&ffn,  g_ffn);
    cudaGetSymbolAddress((void**)&wh,   g_wh);

    cudaFuncSetAttribute(flash_attn, cudaFuncAttributeMaxDynamicSharedMemorySize,
                         FLASH_SMEM);

    // ---- per-replay weight transpose + fp16 convert into g_wh ([N][K]) ----
    dim3 tb(32, 8);
    for (int i = 0; i < 8; i++)
        transpose_w<<<dim3(DMODEL / 32, DMODEL / 32, NLAYER), tb>>>(
            AP[2 * i], wh + (size_t)i * WT_ATTN_TENSOR, DMODEL, DMODEL);
    transpose_w<<<dim3(DFF / 32, DMODEL / 32, NLAYER), tb>>>(
        w1, wh + WT_OFF_W1, DMODEL, DFF);
    transpose_w<<<dim3(DMODEL / 32, DFF / 32, NLAYER), tb>>>(
        w2, wh + WT_OFF_W2, DFF, DMODEL);
    transpose_w<<<dim3(VOC / 32, DMODEL / 32, 1), tb>>>(
        fcw, wh + WT_OFF_FCW, DMODEL, VOC);

    encpe_kernel<<<NE, 256>>>(src, enc);
    embed_kernel<<<NQ, 256>>>(tgt, emb, x);

    const __half* WH[8];
    for (int i = 0; i < 8; i++) WH[i] = wh + (size_t)i * WT_ATTN_TENSOR;
    const __half* w1h = wh + WT_OFF_W1;
    const __half* w2h = wh + WT_OFF_W2;
    const __half* fcwh = wh + WT_OFF_FCW;

    dim3 gDD(DMODEL / BNt, NQ / BMt, 1);
    dim3 gDD3(DMODEL / BNt, NQ / BMt, 3);
    dim3 gFF(DFF / BNt, NQ / BMt, 1);

    for (int l = 0; l < NLAYER; l++) {
        size_t ow = (size_t)l * DMODEL * DMODEL, ob = (size_t)l * DMODEL;
        size_t ow1 = (size_t)l * DMODEL * DFF, ob1 = (size_t)l * DFF;

        // ---- self attention: batched QKV ----
        GArg3 qkv = g1(x, WH[0] + ow, AP[1] + ob, q, NQ);
        qkv.W[1] = WH[1] + ow; qkv.Bi[1] = AP[3] + ob; qkv.C[1] = k;
        qkv.W[2] = WH[2] + ow; qkv.Bi[2] = AP[5] + ob; qkv.C[2] = v;
        gemm_f16<<<gDD3, 256>>>(qkv, DMODEL, DMODEL, 0);
        flash_attn<<<dim3(8, NHEAD, Bsz), 128, FLASH_SMEM>>>(q, k, v, attn,
                                                             TGTL, 1, tgt);
        gemm_f16<<<gDD, 256>>>(g1(attn, WH[3] + ow, AP[7] + ob, proj, NQ),
                               DMODEL, DMODEL, 0);
        ln_res<<<NQ, 256>>>(x, proj, n1g + ob, n1b + ob);

        // ---- cross attention: fused Q (on x) + K,V (on enc) ----
        GArg3 ckv = g1(x, WH[4] + ow, AP[9] + ob, q, NQ);
        ckv.A[1] = enc; ckv.W[1] = WH[5] + ow; ckv.Bi[1] = AP[11] + ob; ckv.C[1] = k; ckv.M[1] = NE;
        ckv.A[2] = enc; ckv.W[2] = WH[6] + ow; ckv.Bi[2] = AP[13] + ob; ckv.C[2] = v; ckv.M[2] = NE;
        gemm_f16<<<gDD3, 256>>>(ckv, DMODEL, DMODEL, 0);
        flash_attn<<<dim3(8, NHEAD, Bsz), 128, FLASH_SMEM>>>(q, k, v, attn,
                                                             SRCL, 0, tgt);
        gemm_f16<<<gDD, 256>>>(g1(attn, WH[7] + ow, AP[15] + ob, proj, NQ),
                               DMODEL, DMODEL, 0);
        ln_res<<<NQ, 256>>>(x, proj, n2g + ob, n2b + ob);

        // ---- feed forward ----
        gemm_f16<<<gFF, 256>>>(g1(x, w1h + ow1, b1 + ob1, ffn, NQ),
                               DFF, DMODEL, 1);
        gemm_f16<<<gDD, 256>>>(g1(ffn, w2h + ow1, b2 + ob, proj, NQ),
                               DMODEL, DFF, 0);
        ln_res<<<NQ, 256>>>(x, proj, n3g + ob, n3b + ob);
    }

    // ---- final projection to vocab ----
    gemm_f16<<<dim3(VOC / BNt, NQ / BMt, 1), 256>>>(
        g1(x, fcwh, fcb, (float*)d_out, NQ), VOC, DMODEL, 0);
}